// round 12
// baseline (speedup 1.0000x reference)
#include <cuda_runtime.h>
#include <cuda_bf16.h>
#include <cuda_fp16.h>
#include <cstdint>
#include <mma.h>

#define NN 100000
#define EE 1600000
#define HH 4
#define CC 32
#define DD 128
#define GG 64
#define NEG 0.2f

using namespace nvcuda;

// ---------------- device scratch ----------------
__device__ float g_hA[(size_t)NN * DD];
__device__ float g_hB[(size_t)NN * DD];
__device__ __half g_hlinh[(size_t)NN * DD];      // fp16 hlin (gather operand)
__device__ __nv_bfloat16 g_Ahi[(size_t)NN * DD];
__device__ __nv_bfloat16 g_Alo[(size_t)NN * DD];
__device__ __nv_bfloat16 g_Whi[3 * DD * DD];
__device__ __nv_bfloat16 g_Wlo[3 * DD * DD];
__device__ float g_asrc[NN * HH];
__device__ float g_adst[NN * HH];
__device__ float g_ewp[(size_t)EE * 8];          // per-edge {colb,w0,colb,w1,colb,w2,colb,w3}
__device__ int   g_deg[NN];
__device__ int   g_rowptr[NN + 1];
__device__ int   g_cursor[NN];
__device__ int   g_colb[EE];                     // src << 8 (byte offset into hlin)
__device__ int   g_dstp[EE];                     // dst per CSR slot

__device__ __forceinline__ float lrelu(float x) { return x > 0.f ? x : NEG * x; }

// ---------------- init (zero + W bf16-split fused) ----------------
__global__ void k_zero(float* __restrict__ gout, const float* __restrict__ Ws) {
    int i = blockIdx.x * blockDim.x + threadIdx.x;
    if (i < NN) g_deg[i] = 0;
    if (i < GG * DD) gout[i] = 0.f;
    if (i < 3 * DD * DD) {
        float f = Ws[i];
        __nv_bfloat16 hi = __float2bfloat16(f);
        g_Whi[i] = hi;
        g_Wlo[i] = __float2bfloat16(f - __bfloat162float(hi));
    }
}

__global__ void k_count(const int* __restrict__ ei) {
    int e = blockIdx.x * blockDim.x + threadIdx.x;
    if (e < EE) atomicAdd(&g_deg[ei[EE + e]], 1);
}

// single-block scan over g_deg -> g_rowptr/g_cursor
__global__ __launch_bounds__(1024) void k_scan_one() {
    __shared__ int s[1024];
    const int t = threadIdx.x;
    const int CH = (NN + 1023) / 1024;           // 98
    int beg = t * CH;
    int end = beg + CH;
    if (end > NN) end = NN;
    int sum = 0;
    for (int i = beg; i < end; i++) sum += g_deg[i];
    s[t] = sum;
    __syncthreads();
    for (int off = 1; off < 1024; off <<= 1) {
        int v = (t >= off) ? s[t - off] : 0;
        __syncthreads();
        s[t] += v;
        __syncthreads();
    }
    int run = s[t] - sum;                         // exclusive prefix
    for (int i = beg; i < end; i++) {
        int d = g_deg[i];
        g_rowptr[i] = run;
        g_cursor[i] = run;
        run += d;
    }
    if (t == 0) g_rowptr[NN] = EE;
}

__global__ void k_fill(const int* __restrict__ ei) {
    int e = blockIdx.x * blockDim.x + threadIdx.x;
    if (e < EE) {
        int src = ei[e];
        int dst = ei[EE + e];
        int pos = atomicAdd(&g_cursor[dst], 1);
        g_colb[pos] = src << 8;      // byte offset: src * 256
        g_dstp[pos] = dst;
    }
}

// ---------------- edge-weight pre-pass (per layer): emit {colb, w_h} pairs ----
__global__ __launch_bounds__(256) void k_ew() {
    int e = blockIdx.x * blockDim.x + threadIdx.x;
    if (e >= EE) return;
    int off = g_colb[e];                               // s << 8
    int d = g_dstp[e];
    const float4 a = *(const float4*)((const char*)g_asrc + (off >> 4));  // s*16 bytes
    const float4 ad = *(const float4*)&g_adst[d * 4];
    float w0 = __expf(lrelu(a.x + ad.x));
    float w1 = __expf(lrelu(a.y + ad.y));
    float w2 = __expf(lrelu(a.z + ad.z));
    float w3 = __expf(lrelu(a.w + ad.w));
    float co = __int_as_float(off);
    *(float4*)&g_ewp[(size_t)e * 8]     = make_float4(co, w0, co, w1);
    *(float4*)&g_ewp[(size_t)e * 8 + 4] = make_float4(co, w2, co, w3);
}

// ---------------- layer-0 GEMM [NN,7]@[7,128] + fused alpha ----------------
__global__ __launch_bounds__(128) void k_gemm0(const float* __restrict__ x,
                                               const float* __restrict__ W,
                                               const float* __restrict__ aws,
                                               const float* __restrict__ awd,
                                               __half* __restrict__ outh) {
    __shared__ float Ws[7 * 128];
    __shared__ float xs[8 * 7];
    int t = threadIdx.x;
    int w = t >> 5, lane = t & 31;
    for (int i = t; i < 7 * 128; i += 128) Ws[i] = W[i];
    int base = blockIdx.x * 8;
    for (int i = t; i < 8 * 7; i += 128) {
        int nn = base + i / 7;
        xs[i] = (nn < NN) ? x[nn * 7 + (i % 7)] : 0.f;
    }
    float awsv = aws[t], awdv = awd[t];
    __syncthreads();
    for (int j = 0; j < 8; j++) {
        int n = base + j;
        if (n < NN) {
            float s = 0.f;
#pragma unroll
            for (int k = 0; k < 7; k++) s = fmaf(xs[j * 7 + k], Ws[k * 128 + t], s);
            outh[(size_t)n * DD + t] = __float2half(s);
            float ps = s * awsv, pd = s * awdv;
#pragma unroll
            for (int o = 16; o >= 1; o >>= 1) {
                ps += __shfl_xor_sync(0xffffffffu, ps, o);
                pd += __shfl_xor_sync(0xffffffffu, pd, o);
            }
            if (lane == 0) {
                g_asrc[n * 4 + w] = ps;
                g_adst[n * 4 + w] = pd;
            }
        }
    }
}

// ---------------- layers 1-3 GEMM: wmma bf16 split + fused alpha, fp16 output
#define BSTRIDE 136
#define ASTRIDE 40
#define SMEM_TC2 91136

__global__ __launch_bounds__(256, 2)
void k_gemm_tc(const __nv_bfloat16* __restrict__ Ahi, const __nv_bfloat16* __restrict__ Alo,
               const __nv_bfloat16* __restrict__ Whi, const __nv_bfloat16* __restrict__ Wlo,
               __half* __restrict__ Couth,
               const float* __restrict__ aw_src, const float* __restrict__ aw_dst) {
    extern __shared__ char dsm[];
    float* awsS = (float*)dsm;
    float* awdS = (float*)(dsm + 512);
    __nv_bfloat16* Bh = (__nv_bfloat16*)(dsm + 1024);
    __nv_bfloat16* Bl = (__nv_bfloat16*)(dsm + 35840);
    __nv_bfloat16* Ah = (__nv_bfloat16*)(dsm + 70656);
    __nv_bfloat16* Al = (__nv_bfloat16*)(dsm + 80896);
    const int tid = threadIdx.x;
    const int wid = tid >> 5;
    const int lane = tid & 31;
    const int row0 = blockIdx.x * 128;
    const int warp_m = wid & 3;
    const int warp_n = wid >> 2;

    if (tid < 128) {
        awsS[tid] = aw_src[tid];
        awdS[tid] = aw_dst[tid];
    }
    {
        int br = tid >> 1, cb = (tid & 1) * 64;
        const uint4* sh = (const uint4*)&Whi[br * DD + cb];
        const uint4* sl = (const uint4*)&Wlo[br * DD + cb];
        uint4* dh = (uint4*)&Bh[br * BSTRIDE + cb];
        uint4* dl = (uint4*)&Bl[br * BSTRIDE + cb];
#pragma unroll
        for (int i = 0; i < 8; i++) { dh[i] = sh[i]; dl[i] = sl[i]; }
    }
    const int ar = tid >> 1;
    const int akb = (tid & 1) * 16;
    const size_t agrow = (size_t)min(row0 + ar, NN - 1) * DD;
#define LOAD_A(c)                                                             \
    do {                                                                      \
        const uint4* sh_ = (const uint4*)&Ahi[agrow + (c) * 32 + akb];        \
        const uint4* sl_ = (const uint4*)&Alo[agrow + (c) * 32 + akb];        \
        uint4* dh_ = (uint4*)&Ah[ar * ASTRIDE + akb];                         \
        uint4* dl_ = (uint4*)&Al[ar * ASTRIDE + akb];                         \
        dh_[0] = sh_[0]; dh_[1] = sh_[1];                                     \
        dl_[0] = sl_[0]; dl_[1] = sl_[1];                                     \
    } while (0)

    wmma::fragment<wmma::accumulator, 16, 16, 16, float> acc[2][4];
#pragma unroll
    for (int im = 0; im < 2; im++)
#pragma unroll
        for (int in = 0; in < 4; in++) wmma::fill_fragment(acc[im][in], 0.f);

    LOAD_A(0);
    __syncthreads();

#pragma unroll
    for (int c = 0; c < 4; c++) {
#pragma unroll
        for (int ksl = 0; ksl < 2; ksl++) {
            wmma::fragment<wmma::matrix_a, 16, 16, 16, __nv_bfloat16, wmma::row_major> ah[2], al[2];
#pragma unroll
            for (int im = 0; im < 2; im++) {
                wmma::load_matrix_sync(ah[im], &Ah[(warp_m * 32 + im * 16) * ASTRIDE + ksl * 16], ASTRIDE);
                wmma::load_matrix_sync(al[im], &Al[(warp_m * 32 + im * 16) * ASTRIDE + ksl * 16], ASTRIDE);
            }
            const int krow = c * 32 + ksl * 16;
#pragma unroll
            for (int in = 0; in < 4; in++) {
                wmma::fragment<wmma::matrix_b, 16, 16, 16, __nv_bfloat16, wmma::row_major> bh, bl;
                wmma::load_matrix_sync(bh, &Bh[krow * BSTRIDE + warp_n * 64 + in * 16], BSTRIDE);
                wmma::load_matrix_sync(bl, &Bl[krow * BSTRIDE + warp_n * 64 + in * 16], BSTRIDE);
#pragma unroll
                for (int im = 0; im < 2; im++) {
                    wmma::mma_sync(acc[im][in], ah[im], bh, acc[im][in]);
                    wmma::mma_sync(acc[im][in], al[im], bh, acc[im][in]);
                    wmma::mma_sync(acc[im][in], ah[im], bl, acc[im][in]);
                }
            }
        }
        __syncthreads();
        if (c < 3) {
            LOAD_A(c + 1);
            __syncthreads();
        }
    }

    float* osm = (float*)(dsm + 1024);
#pragma unroll
    for (int im = 0; im < 2; im++)
#pragma unroll
        for (int in = 0; in < 4; in++)
            wmma::store_matrix_sync(&osm[(warp_m * 32 + im * 16) * BSTRIDE + warp_n * 64 + in * 16],
                                    acc[im][in], BSTRIDE, wmma::mem_row_major);
    __syncthreads();

    if (wid < 4) {
        int r = wid * 32 + lane;
        int grow = row0 + r;
        if (grow < NN) {
#pragma unroll
            for (int b = 0; b < 4; b++) {
                float asum = 0.f, dsum = 0.f;
#pragma unroll
                for (int i = 0; i < 32; i++) {
                    float v = osm[r * BSTRIDE + b * 32 + i];
                    asum = fmaf(v, awsS[b * 32 + i], asum);
                    dsum = fmaf(v, awdS[b * 32 + i], dsum);
                }
                g_asrc[grow * 4 + b] = asum;
                g_adst[grow * 4 + b] = dsum;
            }
        }
    }
    for (int idx = tid; idx < 128 * 32; idx += 256) {
        int r = idx >> 5;
        int c4 = (idx & 31) << 2;
        if (row0 + r < NN) {
            float4 v = *(const float4*)&osm[r * BSTRIDE + c4];
            __half2 h0 = __floats2half2_rn(v.x, v.y);
            __half2 h1 = __floats2half2_rn(v.z, v.w);
            uint2 o;
            o.x = *(uint32_t*)&h0;
            o.y = *(uint32_t*)&h1;
            *(uint2*)&Couth[(size_t)(row0 + r) * DD + c4] = o;
        }
    }
#undef LOAD_A
}

// ---------------- fused GAT aggregate layer (pair loads: 2 LDG/edge) --------
__global__ __launch_bounds__(256) void k_gat(const __half* __restrict__ hlin,
                                             const float* __restrict__ hprev,
                                             const float* __restrict__ bias,
                                             const float* __restrict__ gam,
                                             const float* __restrict__ bet,
                                             float* __restrict__ outp, int residual,
                                             int wbf) {
    int n = (blockIdx.x * blockDim.x + threadIdx.x) >> 5;
    if (n >= NN) return;
    const int lane = threadIdx.x & 31;
    const int hd = lane >> 3;
    const int rs = g_rowptr[n], re = g_rowptr[n + 1];

    float4 ad4 = *(const float4*)&g_adst[n * 4];
    float4 as4 = *(const float4*)&g_asrc[n * 4];

    float wslf;
    {
        float lx = (hd == 0) ? (as4.x + ad4.x) : (hd == 1) ? (as4.y + ad4.y)
                 : (hd == 2) ? (as4.z + ad4.z) : (as4.w + ad4.w);
        wslf = __expf(lrelu(lx));
    }
    float z = wslf;

    const char* hb = (const char*)hlin + lane * 8;   // lane-offset base
    uint2 sp = *(const uint2*)(hb + (size_t)n * 256);
    float2 sf01 = __half22float2(*(__half2*)&sp.x);
    float2 sf23 = __half22float2(*(__half2*)&sp.y);
    float a0 = sf01.x * wslf, a1 = sf01.y * wslf, a2 = sf23.x * wslf, a3 = sf23.y * wslf;

    const float2* pw = (const float2*)g_ewp + hd;    // pair stream for my head

#pragma unroll 8
    for (int e = rs; e < re; e++) {
        float2 cw = __ldg(&pw[(size_t)e * 4]);       // {colb, w_hd} in one LDG.64
        float wj = cw.y;
        uint2 p = *(const uint2*)(hb + __float_as_int(cw.x));
        float2 f01 = __half22float2(*(__half2*)&p.x);
        float2 f23 = __half22float2(*(__half2*)&p.y);
        a0 = fmaf(f01.x, wj, a0);
        a1 = fmaf(f01.y, wj, a1);
        a2 = fmaf(f23.x, wj, a2);
        a3 = fmaf(f23.y, wj, a3);
        z += wj;
    }
    float invz = 1.f / (z + 1e-16f);
    a0 *= invz; a1 *= invz; a2 *= invz; a3 *= invz;

    float4 bv = *(const float4*)&bias[lane * 4];
    a0 += bv.x; a1 += bv.y; a2 += bv.z; a3 += bv.w;
    float sm = a0 + a1 + a2 + a3;
#pragma unroll
    for (int o = 16; o >= 1; o >>= 1) sm += __shfl_xor_sync(0xffffffffu, sm, o);
    float mean = sm * (1.f / DD);
    float d0 = a0 - mean, d1 = a1 - mean, d2 = a2 - mean, d3 = a3 - mean;
    float sq = d0 * d0 + d1 * d1 + d2 * d2 + d3 * d3;
#pragma unroll
    for (int o = 16; o >= 1; o >>= 1) sq += __shfl_xor_sync(0xffffffffu, sq, o);
    float rstd = rsqrtf(sq * (1.f / DD) + 1e-5f);
    float4 gv = *(const float4*)&gam[lane * 4];
    float4 bev = *(const float4*)&bet[lane * 4];
    float v0 = d0 * rstd * gv.x + bev.x;
    float v1 = d1 * rstd * gv.y + bev.y;
    float v2 = d2 * rstd * gv.z + bev.z;
    float v3 = d3 * rstd * gv.w + bev.w;
    v0 = v0 > 0.f ? v0 : __expf(v0) - 1.f;
    v1 = v1 > 0.f ? v1 : __expf(v1) - 1.f;
    v2 = v2 > 0.f ? v2 : __expf(v2) - 1.f;
    v3 = v3 > 0.f ? v3 : __expf(v3) - 1.f;
    if (residual) {
        float4 pv = *(const float4*)&hprev[(size_t)n * DD + lane * 4];
        v0 += pv.x; v1 += pv.y; v2 += pv.z; v3 += pv.w;
    }
    *(float4*)&outp[(size_t)n * DD + lane * 4] = make_float4(v0, v1, v2, v3);

    if (wbf) {
        __nv_bfloat16 h0 = __float2bfloat16(v0);
        __nv_bfloat16 h1 = __float2bfloat16(v1);
        __nv_bfloat16 h2 = __float2bfloat16(v2);
        __nv_bfloat16 h3 = __float2bfloat16(v3);
        __nv_bfloat16 l0 = __float2bfloat16(v0 - __bfloat162float(h0));
        __nv_bfloat16 l1 = __float2bfloat16(v1 - __bfloat162float(h1));
        __nv_bfloat16 l2 = __float2bfloat16(v2 - __bfloat162float(h2));
        __nv_bfloat16 l3 = __float2bfloat16(v3 - __bfloat162float(h3));
        uint2 ph, pl;
        ph.x = (uint32_t)__bfloat16_as_ushort(h0) | ((uint32_t)__bfloat16_as_ushort(h1) << 16);
        ph.y = (uint32_t)__bfloat16_as_ushort(h2) | ((uint32_t)__bfloat16_as_ushort(h3) << 16);
        pl.x = (uint32_t)__bfloat16_as_ushort(l0) | ((uint32_t)__bfloat16_as_ushort(l1) << 16);
        pl.y = (uint32_t)__bfloat16_as_ushort(l2) | ((uint32_t)__bfloat16_as_ushort(l3) << 16);
        *(uint2*)&g_Ahi[(size_t)n * DD + lane * 4] = ph;
        *(uint2*)&g_Alo[(size_t)n * DD + lane * 4] = pl;
    }
}

// ---------------- graph pooling ----------------
__global__ __launch_bounds__(128) void k_pool(const float* __restrict__ ne,
                                              const int* __restrict__ batch,
                                              float* __restrict__ gout) {
    int base = blockIdx.x * 128;
    if (base >= NN) return;
    int d = threadIdx.x;
    int end = base + 128;
    if (end > NN) end = NN;
    float acc = 0.f;
    int cg = __ldg(&batch[base]);
    for (int n = base; n < end; n++) {
        int gidx = __ldg(&batch[n]);
        if (gidx != cg) {
            atomicAdd(&gout[cg * DD + d], acc);
            acc = 0.f;
            cg = gidx;
        }
        acc += ne[(size_t)n * DD + d];
    }
    atomicAdd(&gout[cg * DD + d], acc);
}

// per-graph counts via binary search on sorted batch
__global__ void k_final(float* __restrict__ gout, const int* __restrict__ batch) {
    int g = blockIdx.x;
    int d = threadIdx.x;
    __shared__ int cnt_s;
    if (d == 0) {
        int lo = 0, hi = NN;
        while (lo < hi) { int m = (lo + hi) >> 1; if (batch[m] < g) lo = m + 1; else hi = m; }
        int lb = lo;
        lo = lb; hi = NN;
        while (lo < hi) { int m = (lo + hi) >> 1; if (batch[m] < g + 1) lo = m + 1; else hi = m; }
        cnt_s = lo - lb;
    }
    __syncthreads();
    gout[g * DD + d] /= fmaxf((float)cnt_s, 1.f);
}

// ---------------- host launch ----------------
extern "C" void kernel_launch(void* const* d_in, const int* in_sizes, int n_in,
                              void* d_out, int out_size) {
    const float* x    = (const float*)d_in[0];
    const int*   ei   = (const int*)d_in[1];
    const int*   batch= (const int*)d_in[2];
    const float* W0   = (const float*)d_in[3];
    const float* as0  = (const float*)d_in[4];
    const float* ad0  = (const float*)d_in[5];
    const float* b0   = (const float*)d_in[6];
    const float* Ws   = (const float*)d_in[7];
    const float* asr  = (const float*)d_in[8];
    const float* ads  = (const float*)d_in[9];
    const float* bs   = (const float*)d_in[10];
    const float* lng  = (const float*)d_in[11];
    const float* lnb  = (const float*)d_in[12];
    float* out  = (float*)d_out;
    float* gout = out + (size_t)NN * DD;

    float *hA, *hB;
    __half* hlinh;
    cudaGetSymbolAddress((void**)&hA, g_hA);
    cudaGetSymbolAddress((void**)&hB, g_hB);
    cudaGetSymbolAddress((void**)&hlinh, g_hlinh);
    __nv_bfloat16 *Ahi, *Alo, *Whi, *Wlo;
    cudaGetSymbolAddress((void**)&Ahi, g_Ahi);
    cudaGetSymbolAddress((void**)&Alo, g_Alo);
    cudaGetSymbolAddress((void**)&Whi, g_Whi);
    cudaGetSymbolAddress((void**)&Wlo, g_Wlo);

    cudaFuncSetAttribute(k_gemm_tc, cudaFuncAttributeMaxDynamicSharedMemorySize, SMEM_TC2);

    // CSR build + init
    k_zero<<<(NN + 255) / 256, 256>>>(gout, Ws);
    k_count<<<(EE + 255) / 256, 256>>>(ei);
    k_scan_one<<<1, 1024>>>();
    k_fill<<<(EE + 255) / 256, 256>>>(ei);

    // layer 0 (alpha fused into gemm0; edge weight pairs precomputed)
    k_gemm0<<<(NN + 7) / 8, 128>>>(x, W0, as0, ad0, hlinh);
    k_ew<<<(EE + 255) / 256, 256>>>();
    k_gat<<<(NN * 32 + 255) / 256, 256>>>(hlinh, nullptr, b0, lng, lnb, hA, 0, 1);

    // layers 1..3
    const float* cur = hA;
    for (int l = 1; l < 4; l++) {
        float* nxt = (l == 3) ? out : ((l & 1) ? hB : hA);
        k_gemm_tc<<<(NN + 127) / 128, 256, SMEM_TC2>>>(
            Ahi, Alo, Whi + (size_t)(l - 1) * DD * DD, Wlo + (size_t)(l - 1) * DD * DD,
            hlinh, asr + (l - 1) * DD, ads + (l - 1) * DD);
        k_ew<<<(EE + 255) / 256, 256>>>();
        k_gat<<<(NN * 32 + 255) / 256, 256>>>(hlinh, cur, bs + (l - 1) * DD,
                                              lng + l * DD, lnb + l * DD, nxt, 1,
                                              (l < 3) ? 1 : 0);
        cur = nxt;
    }

    // graph mean pooling
    k_pool<<<(NN + 127) / 128, 128>>>(out, batch, gout);
    k_final<<<GG, 128>>>(gout, batch);
}

// round 13
// speedup vs baseline: 1.7570x; 1.7570x over previous
#include <cuda_runtime.h>
#include <cuda_bf16.h>
#include <cuda_fp16.h>
#include <cstdint>
#include <mma.h>

#define NN 100000
#define EE 1600000
#define HH 4
#define CC 32
#define DD 128
#define GG 64
#define NEG 0.2f
#define NB1 ((NN + 1023) / 1024)

using namespace nvcuda;

// ---------------- device scratch ----------------
__device__ float g_hA[(size_t)NN * DD];
__device__ float g_hB[(size_t)NN * DD];
__device__ __half g_hlinh[(size_t)NN * DD];      // fp16 hlin (gather operand)
__device__ __nv_bfloat16 g_Ahi[(size_t)NN * DD];
__device__ __nv_bfloat16 g_Alo[(size_t)NN * DD];
__device__ __nv_bfloat16 g_Whi[3 * DD * DD];
__device__ __nv_bfloat16 g_Wlo[3 * DD * DD];
__device__ float g_asrc[NN * HH];
__device__ float g_adst[NN * HH];
__device__ float g_ewp[(size_t)EE * 8];          // per-edge {colb,w0,colb,w1,colb,w2,colb,w3}
__device__ int   g_deg[NN];
__device__ int   g_rowptr[NN + 1];
__device__ int   g_cursor[NN];
__device__ int   g_colb[EE];                     // src << 8 (byte offset into hlin)
__device__ int   g_dstp[EE];                     // dst per CSR slot
__device__ int   g_bsums[128];

__device__ __forceinline__ float lrelu(float x) { return x > 0.f ? x : NEG * x; }

// ---------------- init (zero + W bf16-split fused) ----------------
__global__ void k_zero(float* __restrict__ gout, const float* __restrict__ Ws) {
    int i = blockIdx.x * blockDim.x + threadIdx.x;
    if (i < NN) g_deg[i] = 0;
    if (i < GG * DD) gout[i] = 0.f;
    if (i < 3 * DD * DD) {
        float f = Ws[i];
        __nv_bfloat16 hi = __float2bfloat16(f);
        g_Whi[i] = hi;
        g_Wlo[i] = __float2bfloat16(f - __bfloat162float(hi));
    }
}

__global__ void k_count(const int* __restrict__ ei) {
    int e = blockIdx.x * blockDim.x + threadIdx.x;
    if (e < EE) atomicAdd(&g_deg[ei[EE + e]], 1);
}

__global__ void k_scan_block() {
    __shared__ int s[1024];
    int i = blockIdx.x * 1024 + threadIdx.x;
    int v = (i < NN) ? g_deg[i] : 0;
    s[threadIdx.x] = v;
    __syncthreads();
    for (int off = 1; off < 1024; off <<= 1) {
        int t = (threadIdx.x >= off) ? s[threadIdx.x - off] : 0;
        __syncthreads();
        s[threadIdx.x] += t;
        __syncthreads();
    }
    if (i < NN) g_rowptr[i] = s[threadIdx.x] - v;
    if (threadIdx.x == 1023) g_bsums[blockIdx.x] = s[1023];
}

__global__ void k_scan_bsums() {
    __shared__ int s[128];
    int t = threadIdx.x;
    int v = (t < NB1) ? g_bsums[t] : 0;
    s[t] = v;
    __syncthreads();
    for (int off = 1; off < 128; off <<= 1) {
        int u = (t >= off) ? s[t - off] : 0;
        __syncthreads();
        s[t] += u;
        __syncthreads();
    }
    if (t < NB1) g_bsums[t] = s[t] - v;
}

__global__ void k_scan_add() {
    int i = blockIdx.x * blockDim.x + threadIdx.x;
    if (i < NN) {
        int v = g_rowptr[i] + g_bsums[i >> 10];
        g_rowptr[i] = v;
        g_cursor[i] = v;
    }
    if (i == 0) g_rowptr[NN] = EE;
}

__global__ void k_fill(const int* __restrict__ ei) {
    int e = blockIdx.x * blockDim.x + threadIdx.x;
    if (e < EE) {
        int src = ei[e];
        int dst = ei[EE + e];
        int pos = atomicAdd(&g_cursor[dst], 1);
        g_colb[pos] = src << 8;      // byte offset: src * 256
        g_dstp[pos] = dst;
    }
}

// ---------------- edge-weight pre-pass (per layer): emit {colb, w_h} pairs ----
__global__ __launch_bounds__(256) void k_ew() {
    int e = blockIdx.x * blockDim.x + threadIdx.x;
    if (e >= EE) return;
    int off = g_colb[e];                               // s << 8
    int d = g_dstp[e];
    const float4 a = *(const float4*)((const char*)g_asrc + (off >> 4));  // s*16 bytes
    const float4 ad = *(const float4*)&g_adst[d * 4];
    float w0 = __expf(lrelu(a.x + ad.x));
    float w1 = __expf(lrelu(a.y + ad.y));
    float w2 = __expf(lrelu(a.z + ad.z));
    float w3 = __expf(lrelu(a.w + ad.w));
    float co = __int_as_float(off);
    *(float4*)&g_ewp[(size_t)e * 8]     = make_float4(co, w0, co, w1);
    *(float4*)&g_ewp[(size_t)e * 8 + 4] = make_float4(co, w2, co, w3);
}

// ---------------- layer-0 GEMM [NN,7]@[7,128] + fused alpha ----------------
__global__ __launch_bounds__(128) void k_gemm0(const float* __restrict__ x,
                                               const float* __restrict__ W,
                                               const float* __restrict__ aws,
                                               const float* __restrict__ awd,
                                               __half* __restrict__ outh) {
    __shared__ float Ws[7 * 128];
    __shared__ float xs[8 * 7];
    int t = threadIdx.x;
    int w = t >> 5, lane = t & 31;
    for (int i = t; i < 7 * 128; i += 128) Ws[i] = W[i];
    int base = blockIdx.x * 8;
    for (int i = t; i < 8 * 7; i += 128) {
        int nn = base + i / 7;
        xs[i] = (nn < NN) ? x[nn * 7 + (i % 7)] : 0.f;
    }
    float awsv = aws[t], awdv = awd[t];
    __syncthreads();
    for (int j = 0; j < 8; j++) {
        int n = base + j;
        if (n < NN) {
            float s = 0.f;
#pragma unroll
            for (int k = 0; k < 7; k++) s = fmaf(xs[j * 7 + k], Ws[k * 128 + t], s);
            outh[(size_t)n * DD + t] = __float2half(s);
            float ps = s * awsv, pd = s * awdv;
#pragma unroll
            for (int o = 16; o >= 1; o >>= 1) {
                ps += __shfl_xor_sync(0xffffffffu, ps, o);
                pd += __shfl_xor_sync(0xffffffffu, pd, o);
            }
            if (lane == 0) {
                g_asrc[n * 4 + w] = ps;
                g_adst[n * 4 + w] = pd;
            }
        }
    }
}

// ---------------- layers 1-3 GEMM: wmma bf16 split + fused alpha, fp16 output
#define BSTRIDE 136
#define ASTRIDE 40
#define SMEM_TC2 91136

__global__ __launch_bounds__(256, 2)
void k_gemm_tc(const __nv_bfloat16* __restrict__ Ahi, const __nv_bfloat16* __restrict__ Alo,
               const __nv_bfloat16* __restrict__ Whi, const __nv_bfloat16* __restrict__ Wlo,
               __half* __restrict__ Couth,
               const float* __restrict__ aw_src, const float* __restrict__ aw_dst) {
    extern __shared__ char dsm[];
    float* awsS = (float*)dsm;
    float* awdS = (float*)(dsm + 512);
    __nv_bfloat16* Bh = (__nv_bfloat16*)(dsm + 1024);
    __nv_bfloat16* Bl = (__nv_bfloat16*)(dsm + 35840);
    __nv_bfloat16* Ah = (__nv_bfloat16*)(dsm + 70656);
    __nv_bfloat16* Al = (__nv_bfloat16*)(dsm + 80896);
    const int tid = threadIdx.x;
    const int wid = tid >> 5;
    const int lane = tid & 31;
    const int row0 = blockIdx.x * 128;
    const int warp_m = wid & 3;
    const int warp_n = wid >> 2;

    if (tid < 128) {
        awsS[tid] = aw_src[tid];
        awdS[tid] = aw_dst[tid];
    }
    {
        int br = tid >> 1, cb = (tid & 1) * 64;
        const uint4* sh = (const uint4*)&Whi[br * DD + cb];
        const uint4* sl = (const uint4*)&Wlo[br * DD + cb];
        uint4* dh = (uint4*)&Bh[br * BSTRIDE + cb];
        uint4* dl = (uint4*)&Bl[br * BSTRIDE + cb];
#pragma unroll
        for (int i = 0; i < 8; i++) { dh[i] = sh[i]; dl[i] = sl[i]; }
    }
    const int ar = tid >> 1;
    const int akb = (tid & 1) * 16;
    const size_t agrow = (size_t)min(row0 + ar, NN - 1) * DD;
#define LOAD_A(c)                                                             \
    do {                                                                      \
        const uint4* sh_ = (const uint4*)&Ahi[agrow + (c) * 32 + akb];        \
        const uint4* sl_ = (const uint4*)&Alo[agrow + (c) * 32 + akb];        \
        uint4* dh_ = (uint4*)&Ah[ar * ASTRIDE + akb];                         \
        uint4* dl_ = (uint4*)&Al[ar * ASTRIDE + akb];                         \
        dh_[0] = sh_[0]; dh_[1] = sh_[1];                                     \
        dl_[0] = sl_[0]; dl_[1] = sl_[1];                                     \
    } while (0)

    wmma::fragment<wmma::accumulator, 16, 16, 16, float> acc[2][4];
#pragma unroll
    for (int im = 0; im < 2; im++)
#pragma unroll
        for (int in = 0; in < 4; in++) wmma::fill_fragment(acc[im][in], 0.f);

    LOAD_A(0);
    __syncthreads();

#pragma unroll
    for (int c = 0; c < 4; c++) {
#pragma unroll
        for (int ksl = 0; ksl < 2; ksl++) {
            wmma::fragment<wmma::matrix_a, 16, 16, 16, __nv_bfloat16, wmma::row_major> ah[2], al[2];
#pragma unroll
            for (int im = 0; im < 2; im++) {
                wmma::load_matrix_sync(ah[im], &Ah[(warp_m * 32 + im * 16) * ASTRIDE + ksl * 16], ASTRIDE);
                wmma::load_matrix_sync(al[im], &Al[(warp_m * 32 + im * 16) * ASTRIDE + ksl * 16], ASTRIDE);
            }
            const int krow = c * 32 + ksl * 16;
#pragma unroll
            for (int in = 0; in < 4; in++) {
                wmma::fragment<wmma::matrix_b, 16, 16, 16, __nv_bfloat16, wmma::row_major> bh, bl;
                wmma::load_matrix_sync(bh, &Bh[krow * BSTRIDE + warp_n * 64 + in * 16], BSTRIDE);
                wmma::load_matrix_sync(bl, &Bl[krow * BSTRIDE + warp_n * 64 + in * 16], BSTRIDE);
#pragma unroll
                for (int im = 0; im < 2; im++) {
                    wmma::mma_sync(acc[im][in], ah[im], bh, acc[im][in]);
                    wmma::mma_sync(acc[im][in], al[im], bh, acc[im][in]);
                    wmma::mma_sync(acc[im][in], ah[im], bl, acc[im][in]);
                }
            }
        }
        __syncthreads();
        if (c < 3) {
            LOAD_A(c + 1);
            __syncthreads();
        }
    }

    float* osm = (float*)(dsm + 1024);
#pragma unroll
    for (int im = 0; im < 2; im++)
#pragma unroll
        for (int in = 0; in < 4; in++)
            wmma::store_matrix_sync(&osm[(warp_m * 32 + im * 16) * BSTRIDE + warp_n * 64 + in * 16],
                                    acc[im][in], BSTRIDE, wmma::mem_row_major);
    __syncthreads();

    if (wid < 4) {
        int r = wid * 32 + lane;
        int grow = row0 + r;
        if (grow < NN) {
#pragma unroll
            for (int b = 0; b < 4; b++) {
                float asum = 0.f, dsum = 0.f;
#pragma unroll
                for (int i = 0; i < 32; i++) {
                    float v = osm[r * BSTRIDE + b * 32 + i];
                    asum = fmaf(v, awsS[b * 32 + i], asum);
                    dsum = fmaf(v, awdS[b * 32 + i], dsum);
                }
                g_asrc[grow * 4 + b] = asum;
                g_adst[grow * 4 + b] = dsum;
            }
        }
    }
    for (int idx = tid; idx < 128 * 32; idx += 256) {
        int r = idx >> 5;
        int c4 = (idx & 31) << 2;
        if (row0 + r < NN) {
            float4 v = *(const float4*)&osm[r * BSTRIDE + c4];
            __half2 h0 = __floats2half2_rn(v.x, v.y);
            __half2 h1 = __floats2half2_rn(v.z, v.w);
            uint2 o;
            o.x = *(uint32_t*)&h0;
            o.y = *(uint32_t*)&h1;
            *(uint2*)&Couth[(size_t)(row0 + r) * DD + c4] = o;
        }
    }
#undef LOAD_A
}

// ---------------- fused GAT aggregate layer (pair loads: 2 LDG/edge) --------
__global__ __launch_bounds__(256) void k_gat(const __half* __restrict__ hlin,
                                             const float* __restrict__ hprev,
                                             const float* __restrict__ bias,
                                             const float* __restrict__ gam,
                                             const float* __restrict__ bet,
                                             float* __restrict__ outp, int residual,
                                             int wbf) {
    int n = (blockIdx.x * blockDim.x + threadIdx.x) >> 5;
    if (n >= NN) return;
    const int lane = threadIdx.x & 31;
    const int hd = lane >> 3;
    const int rs = g_rowptr[n], re = g_rowptr[n + 1];

    float4 ad4 = *(const float4*)&g_adst[n * 4];
    float4 as4 = *(const float4*)&g_asrc[n * 4];

    float wslf;
    {
        float lx = (hd == 0) ? (as4.x + ad4.x) : (hd == 1) ? (as4.y + ad4.y)
                 : (hd == 2) ? (as4.z + ad4.z) : (as4.w + ad4.w);
        wslf = __expf(lrelu(lx));
    }
    float z = wslf;

    const char* hb = (const char*)hlin + lane * 8;   // lane-offset base
    uint2 sp = *(const uint2*)(hb + (size_t)n * 256);
    float2 sf01 = __half22float2(*(__half2*)&sp.x);
    float2 sf23 = __half22float2(*(__half2*)&sp.y);
    float a0 = sf01.x * wslf, a1 = sf01.y * wslf, a2 = sf23.x * wslf, a3 = sf23.y * wslf;

    const float2* pw = (const float2*)g_ewp + hd;    // pair stream for my head

#pragma unroll 8
    for (int e = rs; e < re; e++) {
        float2 cw = __ldg(&pw[(size_t)e * 4]);       // {colb, w_hd} in one LDG.64
        float wj = cw.y;
        uint2 p = *(const uint2*)(hb + __float_as_int(cw.x));
        float2 f01 = __half22float2(*(__half2*)&p.x);
        float2 f23 = __half22float2(*(__half2*)&p.y);
        a0 = fmaf(f01.x, wj, a0);
        a1 = fmaf(f01.y, wj, a1);
        a2 = fmaf(f23.x, wj, a2);
        a3 = fmaf(f23.y, wj, a3);
        z += wj;
    }
    float invz = 1.f / (z + 1e-16f);
    a0 *= invz; a1 *= invz; a2 *= invz; a3 *= invz;

    float4 bv = *(const float4*)&bias[lane * 4];
    a0 += bv.x; a1 += bv.y; a2 += bv.z; a3 += bv.w;
    float sm = a0 + a1 + a2 + a3;
#pragma unroll
    for (int o = 16; o >= 1; o >>= 1) sm += __shfl_xor_sync(0xffffffffu, sm, o);
    float mean = sm * (1.f / DD);
    float d0 = a0 - mean, d1 = a1 - mean, d2 = a2 - mean, d3 = a3 - mean;
    float sq = d0 * d0 + d1 * d1 + d2 * d2 + d3 * d3;
#pragma unroll
    for (int o = 16; o >= 1; o >>= 1) sq += __shfl_xor_sync(0xffffffffu, sq, o);
    float rstd = rsqrtf(sq * (1.f / DD) + 1e-5f);
    float4 gv = *(const float4*)&gam[lane * 4];
    float4 bev = *(const float4*)&bet[lane * 4];
    float v0 = d0 * rstd * gv.x + bev.x;
    float v1 = d1 * rstd * gv.y + bev.y;
    float v2 = d2 * rstd * gv.z + bev.z;
    float v3 = d3 * rstd * gv.w + bev.w;
    v0 = v0 > 0.f ? v0 : __expf(v0) - 1.f;
    v1 = v1 > 0.f ? v1 : __expf(v1) - 1.f;
    v2 = v2 > 0.f ? v2 : __expf(v2) - 1.f;
    v3 = v3 > 0.f ? v3 : __expf(v3) - 1.f;
    if (residual) {
        float4 pv = *(const float4*)&hprev[(size_t)n * DD + lane * 4];
        v0 += pv.x; v1 += pv.y; v2 += pv.z; v3 += pv.w;
    }
    *(float4*)&outp[(size_t)n * DD + lane * 4] = make_float4(v0, v1, v2, v3);

    if (wbf) {
        __nv_bfloat16 h0 = __float2bfloat16(v0);
        __nv_bfloat16 h1 = __float2bfloat16(v1);
        __nv_bfloat16 h2 = __float2bfloat16(v2);
        __nv_bfloat16 h3 = __float2bfloat16(v3);
        __nv_bfloat16 l0 = __float2bfloat16(v0 - __bfloat162float(h0));
        __nv_bfloat16 l1 = __float2bfloat16(v1 - __bfloat162float(h1));
        __nv_bfloat16 l2 = __float2bfloat16(v2 - __bfloat162float(h2));
        __nv_bfloat16 l3 = __float2bfloat16(v3 - __bfloat162float(h3));
        uint2 ph, pl;
        ph.x = (uint32_t)__bfloat16_as_ushort(h0) | ((uint32_t)__bfloat16_as_ushort(h1) << 16);
        ph.y = (uint32_t)__bfloat16_as_ushort(h2) | ((uint32_t)__bfloat16_as_ushort(h3) << 16);
        pl.x = (uint32_t)__bfloat16_as_ushort(l0) | ((uint32_t)__bfloat16_as_ushort(l1) << 16);
        pl.y = (uint32_t)__bfloat16_as_ushort(l2) | ((uint32_t)__bfloat16_as_ushort(l3) << 16);
        *(uint2*)&g_Ahi[(size_t)n * DD + lane * 4] = ph;
        *(uint2*)&g_Alo[(size_t)n * DD + lane * 4] = pl;
    }
}

// ---------------- graph pooling ----------------
__global__ __launch_bounds__(128) void k_pool(const float* __restrict__ ne,
                                              const int* __restrict__ batch,
                                              float* __restrict__ gout) {
    int base = blockIdx.x * 128;
    if (base >= NN) return;
    int d = threadIdx.x;
    int end = base + 128;
    if (end > NN) end = NN;
    float acc = 0.f;
    int cg = __ldg(&batch[base]);
    for (int n = base; n < end; n++) {
        int gidx = __ldg(&batch[n]);
        if (gidx != cg) {
            atomicAdd(&gout[cg * DD + d], acc);
            acc = 0.f;
            cg = gidx;
        }
        acc += ne[(size_t)n * DD + d];
    }
    atomicAdd(&gout[cg * DD + d], acc);
}

// per-graph counts via binary search on sorted batch
__global__ void k_final(float* __restrict__ gout, const int* __restrict__ batch) {
    int g = blockIdx.x;
    int d = threadIdx.x;
    __shared__ int cnt_s;
    if (d == 0) {
        int lo = 0, hi = NN;
        while (lo < hi) { int m = (lo + hi) >> 1; if (batch[m] < g) lo = m + 1; else hi = m; }
        int lb = lo;
        lo = lb; hi = NN;
        while (lo < hi) { int m = (lo + hi) >> 1; if (batch[m] < g + 1) lo = m + 1; else hi = m; }
        cnt_s = lo - lb;
    }
    __syncthreads();
    gout[g * DD + d] /= fmaxf((float)cnt_s, 1.f);
}

// ---------------- host launch ----------------
extern "C" void kernel_launch(void* const* d_in, const int* in_sizes, int n_in,
                              void* d_out, int out_size) {
    const float* x    = (const float*)d_in[0];
    const int*   ei   = (const int*)d_in[1];
    const int*   batch= (const int*)d_in[2];
    const float* W0   = (const float*)d_in[3];
    const float* as0  = (const float*)d_in[4];
    const float* ad0  = (const float*)d_in[5];
    const float* b0   = (const float*)d_in[6];
    const float* Ws   = (const float*)d_in[7];
    const float* asr  = (const float*)d_in[8];
    const float* ads  = (const float*)d_in[9];
    const float* bs   = (const float*)d_in[10];
    const float* lng  = (const float*)d_in[11];
    const float* lnb  = (const float*)d_in[12];
    float* out  = (float*)d_out;
    float* gout = out + (size_t)NN * DD;

    float *hA, *hB;
    __half* hlinh;
    cudaGetSymbolAddress((void**)&hA, g_hA);
    cudaGetSymbolAddress((void**)&hB, g_hB);
    cudaGetSymbolAddress((void**)&hlinh, g_hlinh);
    __nv_bfloat16 *Ahi, *Alo, *Whi, *Wlo;
    cudaGetSymbolAddress((void**)&Ahi, g_Ahi);
    cudaGetSymbolAddress((void**)&Alo, g_Alo);
    cudaGetSymbolAddress((void**)&Whi, g_Whi);
    cudaGetSymbolAddress((void**)&Wlo, g_Wlo);

    cudaFuncSetAttribute(k_gemm_tc, cudaFuncAttributeMaxDynamicSharedMemorySize, SMEM_TC2);

    // CSR build + init (parallel 3-kernel scan — R11 proven)
    k_zero<<<(NN + 255) / 256, 256>>>(gout, Ws);
    k_count<<<(EE + 255) / 256, 256>>>(ei);
    k_scan_block<<<NB1, 1024>>>();
    k_scan_bsums<<<1, 128>>>();
    k_scan_add<<<(NN + 255) / 256, 256>>>();
    k_fill<<<(EE + 255) / 256, 256>>>(ei);

    // layer 0 (alpha fused into gemm0; edge weight pairs precomputed)
    k_gemm0<<<(NN + 7) / 8, 128>>>(x, W0, as0, ad0, hlinh);
    k_ew<<<(EE + 255) / 256, 256>>>();
    k_gat<<<(NN * 32 + 255) / 256, 256>>>(hlinh, nullptr, b0, lng, lnb, hA, 0, 1);

    // layers 1..3
    const float* cur = hA;
    for (int l = 1; l < 4; l++) {
        float* nxt = (l == 3) ? out : ((l & 1) ? hB : hA);
        k_gemm_tc<<<(NN + 127) / 128, 256, SMEM_TC2>>>(
            Ahi, Alo, Whi + (size_t)(l - 1) * DD * DD, Wlo + (size_t)(l - 1) * DD * DD,
            hlinh, asr + (l - 1) * DD, ads + (l - 1) * DD);
        k_ew<<<(EE + 255) / 256, 256>>>();
        k_gat<<<(NN * 32 + 255) / 256, 256>>>(hlinh, cur, bs + (l - 1) * DD,
                                              lng + l * DD, lnb + l * DD, nxt, 1,
                                              (l < 3) ? 1 : 0);
        cur = nxt;
    }

    // graph mean pooling
    k_pool<<<(NN + 127) / 128, 128>>>(out, batch, gout);
    k_final<<<GG, 128>>>(gout, batch);
}

// round 14
// speedup vs baseline: 2.0075x; 1.1426x over previous
#include <cuda_runtime.h>
#include <cuda_bf16.h>
#include <cuda_fp16.h>
#include <cstdint>
#include <mma.h>

#define NN 100000
#define EE 1600000
#define HH 4
#define CC 32
#define DD 128
#define GG 64
#define NEG 0.2f
#define NB1 ((NN + 1023) / 1024)

using namespace nvcuda;

// ---------------- device scratch ----------------
__device__ float g_hA[(size_t)NN * DD];
__device__ float g_hB[(size_t)NN * DD];
__device__ __half g_hlinh[(size_t)NN * DD];      // fp16 hlin (gather operand)
__device__ __nv_bfloat16 g_Ahi[(size_t)NN * DD];
__device__ __nv_bfloat16 g_Alo[(size_t)NN * DD];
__device__ __nv_bfloat16 g_Whi[3 * DD * DD];
__device__ __nv_bfloat16 g_Wlo[3 * DD * DD];
__device__ float g_asrc[NN * HH];
__device__ float g_adst[NN * HH];
__device__ __half g_ewh[(size_t)EE * 4];         // per-edge softmax weights, fp16 (8 B/edge)
__device__ int   g_deg[NN];
__device__ int   g_rowptr[NN + 1];
__device__ int   g_cursor[NN];
__device__ int   g_colb[EE];                     // src << 8 (byte offset into hlin)
__device__ int   g_dstp[EE];                     // dst per CSR slot
__device__ int   g_bsums[128];

__device__ __forceinline__ float lrelu(float x) { return x > 0.f ? x : NEG * x; }

// ---------------- init (zero + W bf16-split fused) ----------------
__global__ void k_zero(float* __restrict__ gout, const float* __restrict__ Ws) {
    int i = blockIdx.x * blockDim.x + threadIdx.x;
    if (i < NN) g_deg[i] = 0;
    if (i < GG * DD) gout[i] = 0.f;
    if (i < 3 * DD * DD) {
        float f = Ws[i];
        __nv_bfloat16 hi = __float2bfloat16(f);
        g_Whi[i] = hi;
        g_Wlo[i] = __float2bfloat16(f - __bfloat162float(hi));
    }
}

__global__ void k_count(const int* __restrict__ ei) {
    int e = blockIdx.x * blockDim.x + threadIdx.x;
    if (e < EE) atomicAdd(&g_deg[ei[EE + e]], 1);
}

__global__ void k_scan_block() {
    __shared__ int s[1024];
    int i = blockIdx.x * 1024 + threadIdx.x;
    int v = (i < NN) ? g_deg[i] : 0;
    s[threadIdx.x] = v;
    __syncthreads();
    for (int off = 1; off < 1024; off <<= 1) {
        int t = (threadIdx.x >= off) ? s[threadIdx.x - off] : 0;
        __syncthreads();
        s[threadIdx.x] += t;
        __syncthreads();
    }
    if (i < NN) g_rowptr[i] = s[threadIdx.x] - v;
    if (threadIdx.x == 1023) g_bsums[blockIdx.x] = s[1023];
}

__global__ void k_scan_bsums() {
    __shared__ int s[128];
    int t = threadIdx.x;
    int v = (t < NB1) ? g_bsums[t] : 0;
    s[t] = v;
    __syncthreads();
    for (int off = 1; off < 128; off <<= 1) {
        int u = (t >= off) ? s[t - off] : 0;
        __syncthreads();
        s[t] += u;
        __syncthreads();
    }
    if (t < NB1) g_bsums[t] = s[t] - v;
}

__global__ void k_scan_add() {
    int i = blockIdx.x * blockDim.x + threadIdx.x;
    if (i < NN) {
        int v = g_rowptr[i] + g_bsums[i >> 10];
        g_rowptr[i] = v;
        g_cursor[i] = v;
    }
    if (i == 0) g_rowptr[NN] = EE;
}

__global__ void k_fill(const int* __restrict__ ei) {
    int e = blockIdx.x * blockDim.x + threadIdx.x;
    if (e < EE) {
        int src = ei[e];
        int dst = ei[EE + e];
        int pos = atomicAdd(&g_cursor[dst], 1);
        g_colb[pos] = src << 8;      // byte offset: src * 256
        g_dstp[pos] = dst;
    }
}

// ---------------- edge-weight pre-pass (per layer), fp16 output ----------------
__global__ __launch_bounds__(256) void k_ew() {
    int e = blockIdx.x * blockDim.x + threadIdx.x;
    if (e >= EE) return;
    int off = g_colb[e];                               // s << 8
    int d = g_dstp[e];
    const float4 a = *(const float4*)((const char*)g_asrc + (off >> 4));  // s*16 bytes
    const float4 ad = *(const float4*)&g_adst[d * 4];
    float w0 = __expf(lrelu(a.x + ad.x));
    float w1 = __expf(lrelu(a.y + ad.y));
    float w2 = __expf(lrelu(a.z + ad.z));
    float w3 = __expf(lrelu(a.w + ad.w));
    __half2 p01 = __floats2half2_rn(w0, w1);
    __half2 p23 = __floats2half2_rn(w2, w3);
    uint2 o;
    o.x = *(uint32_t*)&p01;
    o.y = *(uint32_t*)&p23;
    *(uint2*)&g_ewh[(size_t)e * 4] = o;
}

// ---------------- layer-0 GEMM [NN,7]@[7,128] + fused alpha ----------------
__global__ __launch_bounds__(128) void k_gemm0(const float* __restrict__ x,
                                               const float* __restrict__ W,
                                               const float* __restrict__ aws,
                                               const float* __restrict__ awd,
                                               __half* __restrict__ outh) {
    __shared__ float Ws[7 * 128];
    __shared__ float xs[8 * 7];
    int t = threadIdx.x;
    int w = t >> 5, lane = t & 31;
    for (int i = t; i < 7 * 128; i += 128) Ws[i] = W[i];
    int base = blockIdx.x * 8;
    for (int i = t; i < 8 * 7; i += 128) {
        int nn = base + i / 7;
        xs[i] = (nn < NN) ? x[nn * 7 + (i % 7)] : 0.f;
    }
    float awsv = aws[t], awdv = awd[t];
    __syncthreads();
    for (int j = 0; j < 8; j++) {
        int n = base + j;
        if (n < NN) {
            float s = 0.f;
#pragma unroll
            for (int k = 0; k < 7; k++) s = fmaf(xs[j * 7 + k], Ws[k * 128 + t], s);
            outh[(size_t)n * DD + t] = __float2half(s);
            float ps = s * awsv, pd = s * awdv;
#pragma unroll
            for (int o = 16; o >= 1; o >>= 1) {
                ps += __shfl_xor_sync(0xffffffffu, ps, o);
                pd += __shfl_xor_sync(0xffffffffu, pd, o);
            }
            if (lane == 0) {
                g_asrc[n * 4 + w] = ps;
                g_adst[n * 4 + w] = pd;
            }
        }
    }
}

// ---------------- layers 1-3 GEMM: wmma bf16 split + fused alpha, fp16 output
#define BSTRIDE 136
#define ASTRIDE 40
#define SMEM_TC2 91136

__global__ __launch_bounds__(256, 2)
void k_gemm_tc(const __nv_bfloat16* __restrict__ Ahi, const __nv_bfloat16* __restrict__ Alo,
               const __nv_bfloat16* __restrict__ Whi, const __nv_bfloat16* __restrict__ Wlo,
               __half* __restrict__ Couth,
               const float* __restrict__ aw_src, const float* __restrict__ aw_dst) {
    extern __shared__ char dsm[];
    float* awsS = (float*)dsm;
    float* awdS = (float*)(dsm + 512);
    __nv_bfloat16* Bh = (__nv_bfloat16*)(dsm + 1024);
    __nv_bfloat16* Bl = (__nv_bfloat16*)(dsm + 35840);
    __nv_bfloat16* Ah = (__nv_bfloat16*)(dsm + 70656);
    __nv_bfloat16* Al = (__nv_bfloat16*)(dsm + 80896);
    const int tid = threadIdx.x;
    const int wid = tid >> 5;
    const int lane = tid & 31;
    const int row0 = blockIdx.x * 128;
    const int warp_m = wid & 3;
    const int warp_n = wid >> 2;

    if (tid < 128) {
        awsS[tid] = aw_src[tid];
        awdS[tid] = aw_dst[tid];
    }
    {
        int br = tid >> 1, cb = (tid & 1) * 64;
        const uint4* sh = (const uint4*)&Whi[br * DD + cb];
        const uint4* sl = (const uint4*)&Wlo[br * DD + cb];
        uint4* dh = (uint4*)&Bh[br * BSTRIDE + cb];
        uint4* dl = (uint4*)&Bl[br * BSTRIDE + cb];
#pragma unroll
        for (int i = 0; i < 8; i++) { dh[i] = sh[i]; dl[i] = sl[i]; }
    }
    const int ar = tid >> 1;
    const int akb = (tid & 1) * 16;
    const size_t agrow = (size_t)min(row0 + ar, NN - 1) * DD;
#define LOAD_A(c)                                                             \
    do {                                                                      \
        const uint4* sh_ = (const uint4*)&Ahi[agrow + (c) * 32 + akb];        \
        const uint4* sl_ = (const uint4*)&Alo[agrow + (c) * 32 + akb];        \
        uint4* dh_ = (uint4*)&Ah[ar * ASTRIDE + akb];                         \
        uint4* dl_ = (uint4*)&Al[ar * ASTRIDE + akb];                         \
        dh_[0] = sh_[0]; dh_[1] = sh_[1];                                     \
        dl_[0] = sl_[0]; dl_[1] = sl_[1];                                     \
    } while (0)

    wmma::fragment<wmma::accumulator, 16, 16, 16, float> acc[2][4];
#pragma unroll
    for (int im = 0; im < 2; im++)
#pragma unroll
        for (int in = 0; in < 4; in++) wmma::fill_fragment(acc[im][in], 0.f);

    LOAD_A(0);
    __syncthreads();

#pragma unroll
    for (int c = 0; c < 4; c++) {
#pragma unroll
        for (int ksl = 0; ksl < 2; ksl++) {
            wmma::fragment<wmma::matrix_a, 16, 16, 16, __nv_bfloat16, wmma::row_major> ah[2], al[2];
#pragma unroll
            for (int im = 0; im < 2; im++) {
                wmma::load_matrix_sync(ah[im], &Ah[(warp_m * 32 + im * 16) * ASTRIDE + ksl * 16], ASTRIDE);
                wmma::load_matrix_sync(al[im], &Al[(warp_m * 32 + im * 16) * ASTRIDE + ksl * 16], ASTRIDE);
            }
            const int krow = c * 32 + ksl * 16;
#pragma unroll
            for (int in = 0; in < 4; in++) {
                wmma::fragment<wmma::matrix_b, 16, 16, 16, __nv_bfloat16, wmma::row_major> bh, bl;
                wmma::load_matrix_sync(bh, &Bh[krow * BSTRIDE + warp_n * 64 + in * 16], BSTRIDE);
                wmma::load_matrix_sync(bl, &Bl[krow * BSTRIDE + warp_n * 64 + in * 16], BSTRIDE);
#pragma unroll
                for (int im = 0; im < 2; im++) {
                    wmma::mma_sync(acc[im][in], ah[im], bh, acc[im][in]);
                    wmma::mma_sync(acc[im][in], al[im], bh, acc[im][in]);
                    wmma::mma_sync(acc[im][in], ah[im], bl, acc[im][in]);
                }
            }
        }
        __syncthreads();
        if (c < 3) {
            LOAD_A(c + 1);
            __syncthreads();
        }
    }

    float* osm = (float*)(dsm + 1024);
#pragma unroll
    for (int im = 0; im < 2; im++)
#pragma unroll
        for (int in = 0; in < 4; in++)
            wmma::store_matrix_sync(&osm[(warp_m * 32 + im * 16) * BSTRIDE + warp_n * 64 + in * 16],
                                    acc[im][in], BSTRIDE, wmma::mem_row_major);
    __syncthreads();

    if (wid < 4) {
        int r = wid * 32 + lane;
        int grow = row0 + r;
        if (grow < NN) {
#pragma unroll
            for (int b = 0; b < 4; b++) {
                float asum = 0.f, dsum = 0.f;
#pragma unroll
                for (int i = 0; i < 32; i++) {
                    float v = osm[r * BSTRIDE + b * 32 + i];
                    asum = fmaf(v, awsS[b * 32 + i], asum);
                    dsum = fmaf(v, awdS[b * 32 + i], dsum);
                }
                g_asrc[grow * 4 + b] = asum;
                g_adst[grow * 4 + b] = dsum;
            }
        }
    }
    for (int idx = tid; idx < 128 * 32; idx += 256) {
        int r = idx >> 5;
        int c4 = (idx & 31) << 2;
        if (row0 + r < NN) {
            float4 v = *(const float4*)&osm[r * BSTRIDE + c4];
            __half2 h0 = __floats2half2_rn(v.x, v.y);
            __half2 h1 = __floats2half2_rn(v.z, v.w);
            uint2 o;
            o.x = *(uint32_t*)&h0;
            o.y = *(uint32_t*)&h1;
            *(uint2*)&Couth[(size_t)(row0 + r) * DD + c4] = o;
        }
    }
#undef LOAD_A
}

// ---------------- fused GAT aggregate layer (weights precomputed, fp16) -----
__global__ __launch_bounds__(256) void k_gat(const __half* __restrict__ hlin,
                                             const float* __restrict__ hprev,
                                             const float* __restrict__ bias,
                                             const float* __restrict__ gam,
                                             const float* __restrict__ bet,
                                             float* __restrict__ outp, int residual,
                                             int wbf) {
    int n = (blockIdx.x * blockDim.x + threadIdx.x) >> 5;
    if (n >= NN) return;
    const int lane = threadIdx.x & 31;
    const int hd = lane >> 3;
    const int rs = g_rowptr[n], re = g_rowptr[n + 1];

    float4 ad4 = *(const float4*)&g_adst[n * 4];
    float4 as4 = *(const float4*)&g_asrc[n * 4];

    float wslf;
    {
        float lx = (hd == 0) ? (as4.x + ad4.x) : (hd == 1) ? (as4.y + ad4.y)
                 : (hd == 2) ? (as4.z + ad4.z) : (as4.w + ad4.w);
        wslf = __expf(lrelu(lx));
    }
    float z = wslf;

    const char* hb = (const char*)hlin + lane * 8;   // lane-offset base
    uint2 sp = *(const uint2*)(hb + (size_t)n * 256);
    float2 sf01 = __half22float2(*(__half2*)&sp.x);
    float2 sf23 = __half22float2(*(__half2*)&sp.y);
    float a0 = sf01.x * wslf, a1 = sf01.y * wslf, a2 = sf23.x * wslf, a3 = sf23.y * wslf;

    const __half* ewp = g_ewh + hd;                  // per-head weight base

#pragma unroll 8
    for (int e = rs; e < re; e++) {
        int off = __ldg(&g_colb[e]);                 // uniform broadcast (L1)
        float wj = __half2float(__ldg(&ewp[(size_t)e * 4]));
        uint2 p = *(const uint2*)(hb + off);
        float2 f01 = __half22float2(*(__half2*)&p.x);
        float2 f23 = __half22float2(*(__half2*)&p.y);
        a0 = fmaf(f01.x, wj, a0);
        a1 = fmaf(f01.y, wj, a1);
        a2 = fmaf(f23.x, wj, a2);
        a3 = fmaf(f23.y, wj, a3);
        z += wj;
    }
    float invz = 1.f / (z + 1e-16f);
    a0 *= invz; a1 *= invz; a2 *= invz; a3 *= invz;

    float4 bv = *(const float4*)&bias[lane * 4];
    a0 += bv.x; a1 += bv.y; a2 += bv.z; a3 += bv.w;
    float sm = a0 + a1 + a2 + a3;
#pragma unroll
    for (int o = 16; o >= 1; o >>= 1) sm += __shfl_xor_sync(0xffffffffu, sm, o);
    float mean = sm * (1.f / DD);
    float d0 = a0 - mean, d1 = a1 - mean, d2 = a2 - mean, d3 = a3 - mean;
    float sq = d0 * d0 + d1 * d1 + d2 * d2 + d3 * d3;
#pragma unroll
    for (int o = 16; o >= 1; o >>= 1) sq += __shfl_xor_sync(0xffffffffu, sq, o);
    float rstd = rsqrtf(sq * (1.f / DD) + 1e-5f);
    float4 gv = *(const float4*)&gam[lane * 4];
    float4 bev = *(const float4*)&bet[lane * 4];
    float v0 = d0 * rstd * gv.x + bev.x;
    float v1 = d1 * rstd * gv.y + bev.y;
    float v2 = d2 * rstd * gv.z + bev.z;
    float v3 = d3 * rstd * gv.w + bev.w;
    v0 = v0 > 0.f ? v0 : __expf(v0) - 1.f;
    v1 = v1 > 0.f ? v1 : __expf(v1) - 1.f;
    v2 = v2 > 0.f ? v2 : __expf(v2) - 1.f;
    v3 = v3 > 0.f ? v3 : __expf(v3) - 1.f;
    if (residual) {
        float4 pv = *(const float4*)&hprev[(size_t)n * DD + lane * 4];
        v0 += pv.x; v1 += pv.y; v2 += pv.z; v3 += pv.w;
    }
    *(float4*)&outp[(size_t)n * DD + lane * 4] = make_float4(v0, v1, v2, v3);

    if (wbf) {
        __nv_bfloat16 h0 = __float2bfloat16(v0);
        __nv_bfloat16 h1 = __float2bfloat16(v1);
        __nv_bfloat16 h2 = __float2bfloat16(v2);
        __nv_bfloat16 h3 = __float2bfloat16(v3);
        __nv_bfloat16 l0 = __float2bfloat16(v0 - __bfloat162float(h0));
        __nv_bfloat16 l1 = __float2bfloat16(v1 - __bfloat162float(h1));
        __nv_bfloat16 l2 = __float2bfloat16(v2 - __bfloat162float(h2));
        __nv_bfloat16 l3 = __float2bfloat16(v3 - __bfloat162float(h3));
        uint2 ph, pl;
        ph.x = (uint32_t)__bfloat16_as_ushort(h0) | ((uint32_t)__bfloat16_as_ushort(h1) << 16);
        ph.y = (uint32_t)__bfloat16_as_ushort(h2) | ((uint32_t)__bfloat16_as_ushort(h3) << 16);
        pl.x = (uint32_t)__bfloat16_as_ushort(l0) | ((uint32_t)__bfloat16_as_ushort(l1) << 16);
        pl.y = (uint32_t)__bfloat16_as_ushort(l2) | ((uint32_t)__bfloat16_as_ushort(l3) << 16);
        *(uint2*)&g_Ahi[(size_t)n * DD + lane * 4] = ph;
        *(uint2*)&g_Alo[(size_t)n * DD + lane * 4] = pl;
    }
}

// ---------------- graph pooling ----------------
__global__ __launch_bounds__(128) void k_pool(const float* __restrict__ ne,
                                              const int* __restrict__ batch,
                                              float* __restrict__ gout) {
    int base = blockIdx.x * 128;
    if (base >= NN) return;
    int d = threadIdx.x;
    int end = base + 128;
    if (end > NN) end = NN;
    float acc = 0.f;
    int cg = __ldg(&batch[base]);
    for (int n = base; n < end; n++) {
        int gidx = __ldg(&batch[n]);
        if (gidx != cg) {
            atomicAdd(&gout[cg * DD + d], acc);
            acc = 0.f;
            cg = gidx;
        }
        acc += ne[(size_t)n * DD + d];
    }
    atomicAdd(&gout[cg * DD + d], acc);
}

// per-graph counts via binary search on sorted batch
__global__ void k_final(float* __restrict__ gout, const int* __restrict__ batch) {
    int g = blockIdx.x;
    int d = threadIdx.x;
    __shared__ int cnt_s;
    if (d == 0) {
        int lo = 0, hi = NN;
        while (lo < hi) { int m = (lo + hi) >> 1; if (batch[m] < g) lo = m + 1; else hi = m; }
        int lb = lo;
        lo = lb; hi = NN;
        while (lo < hi) { int m = (lo + hi) >> 1; if (batch[m] < g + 1) lo = m + 1; else hi = m; }
        cnt_s = lo - lb;
    }
    __syncthreads();
    gout[g * DD + d] /= fmaxf((float)cnt_s, 1.f);
}

// ---------------- host launch ----------------
extern "C" void kernel_launch(void* const* d_in, const int* in_sizes, int n_in,
                              void* d_out, int out_size) {
    const float* x    = (const float*)d_in[0];
    const int*   ei   = (const int*)d_in[1];
    const int*   batch= (const int*)d_in[2];
    const float* W0   = (const float*)d_in[3];
    const float* as0  = (const float*)d_in[4];
    const float* ad0  = (const float*)d_in[5];
    const float* b0   = (const float*)d_in[6];
    const float* Ws   = (const float*)d_in[7];
    const float* asr  = (const float*)d_in[8];
    const float* ads  = (const float*)d_in[9];
    const float* bs   = (const float*)d_in[10];
    const float* lng  = (const float*)d_in[11];
    const float* lnb  = (const float*)d_in[12];
    float* out  = (float*)d_out;
    float* gout = out + (size_t)NN * DD;

    float *hA, *hB;
    __half* hlinh;
    cudaGetSymbolAddress((void**)&hA, g_hA);
    cudaGetSymbolAddress((void**)&hB, g_hB);
    cudaGetSymbolAddress((void**)&hlinh, g_hlinh);
    __nv_bfloat16 *Ahi, *Alo, *Whi, *Wlo;
    cudaGetSymbolAddress((void**)&Ahi, g_Ahi);
    cudaGetSymbolAddress((void**)&Alo, g_Alo);
    cudaGetSymbolAddress((void**)&Whi, g_Whi);
    cudaGetSymbolAddress((void**)&Wlo, g_Wlo);

    cudaFuncSetAttribute(k_gemm_tc, cudaFuncAttributeMaxDynamicSharedMemorySize, SMEM_TC2);

    // CSR build + init (parallel 3-kernel scan)
    k_zero<<<(NN + 255) / 256, 256>>>(gout, Ws);
    k_count<<<(EE + 255) / 256, 256>>>(ei);
    k_scan_block<<<NB1, 1024>>>();
    k_scan_bsums<<<1, 128>>>();
    k_scan_add<<<(NN + 255) / 256, 256>>>();
    k_fill<<<(EE + 255) / 256, 256>>>(ei);

    // layer 0 (alpha fused into gemm0; edge weights precomputed fp16)
    k_gemm0<<<(NN + 7) / 8, 128>>>(x, W0, as0, ad0, hlinh);
    k_ew<<<(EE + 255) / 256, 256>>>();
    k_gat<<<(NN * 32 + 255) / 256, 256>>>(hlinh, nullptr, b0, lng, lnb, hA, 0, 1);

    // layers 1..3
    const float* cur = hA;
    for (int l = 1; l < 4; l++) {
        float* nxt = (l == 3) ? out : ((l & 1) ? hB : hA);
        k_gemm_tc<<<(NN + 127) / 128, 256, SMEM_TC2>>>(
            Ahi, Alo, Whi + (size_t)(l - 1) * DD * DD, Wlo + (size_t)(l - 1) * DD * DD,
            hlinh, asr + (l - 1) * DD, ads + (l - 1) * DD);
        k_ew<<<(EE + 255) / 256, 256>>>();
        k_gat<<<(NN * 32 + 255) / 256, 256>>>(hlinh, cur, bs + (l - 1) * DD,
                                              lng + l * DD, lnb + l * DD, nxt, 1,
                                              (l < 3) ? 1 : 0);
        cur = nxt;
    }

    // graph mean pooling
    k_pool<<<(NN + 127) / 128, 128>>>(out, batch, gout);
    k_final<<<GG, 128>>>(gout, batch);
}

// round 15
// speedup vs baseline: 2.1132x; 1.0526x over previous
#include <cuda_runtime.h>
#include <cuda_fp16.h>
#include <cstdint>
#include <mma.h>

#define NN 100000
#define EE 1600000
#define HH 4
#define CC 32
#define DD 128
#define GG 64
#define NEG 0.2f
#define NB1 ((NN + 1023) / 1024)

using namespace nvcuda;

// ---------------- device scratch ----------------
// node state h stored as fp16 hi/lo pairs (h = hi + lo, exact to 2^-22)
__device__ __half g_hXhi[(size_t)NN * DD];
__device__ __half g_hXlo[(size_t)NN * DD];
__device__ __half g_hYhi[(size_t)NN * DD];
__device__ __half g_hYlo[(size_t)NN * DD];
__device__ __half g_hlinh[(size_t)NN * DD];      // fp16 hlin (gather operand)
__device__ __half g_Whi[3 * DD * DD];
__device__ __half g_Wlo[3 * DD * DD];
__device__ float g_asrc[NN * HH];
__device__ float g_adst[NN * HH];
__device__ __half g_ewh[(size_t)EE * 4];         // per-edge softmax weights, fp16
__device__ int   g_deg[NN];
__device__ int   g_rowptr[NN + 1];
__device__ int   g_cursor[NN];
__device__ int   g_colb[EE];                     // src << 8 (byte offset into hlin)
__device__ int   g_dstp[EE];                     // dst per CSR slot
__device__ int   g_bsums[128];

__device__ __forceinline__ float lrelu(float x) { return x > 0.f ? x : NEG * x; }

// ---------------- init (zero + W fp16-split fused) ----------------
__global__ void k_zero(float* __restrict__ gout, const float* __restrict__ Ws) {
    int i = blockIdx.x * blockDim.x + threadIdx.x;
    if (i < NN) g_deg[i] = 0;
    if (i < GG * DD) gout[i] = 0.f;
    if (i < 3 * DD * DD) {
        float f = Ws[i];
        __half hi = __float2half(f);
        g_Whi[i] = hi;
        g_Wlo[i] = __float2half(f - __half2float(hi));
    }
}

__global__ void k_count(const int* __restrict__ ei) {
    int e = blockIdx.x * blockDim.x + threadIdx.x;
    if (e < EE) atomicAdd(&g_deg[ei[EE + e]], 1);
}

__global__ void k_scan_block() {
    __shared__ int s[1024];
    int i = blockIdx.x * 1024 + threadIdx.x;
    int v = (i < NN) ? g_deg[i] : 0;
    s[threadIdx.x] = v;
    __syncthreads();
    for (int off = 1; off < 1024; off <<= 1) {
        int t = (threadIdx.x >= off) ? s[threadIdx.x - off] : 0;
        __syncthreads();
        s[threadIdx.x] += t;
        __syncthreads();
    }
    if (i < NN) g_rowptr[i] = s[threadIdx.x] - v;
    if (threadIdx.x == 1023) g_bsums[blockIdx.x] = s[1023];
}

__global__ void k_scan_bsums() {
    __shared__ int s[128];
    int t = threadIdx.x;
    int v = (t < NB1) ? g_bsums[t] : 0;
    s[t] = v;
    __syncthreads();
    for (int off = 1; off < 128; off <<= 1) {
        int u = (t >= off) ? s[t - off] : 0;
        __syncthreads();
        s[t] += u;
        __syncthreads();
    }
    if (t < NB1) g_bsums[t] = s[t] - v;
}

__global__ void k_scan_add() {
    int i = blockIdx.x * blockDim.x + threadIdx.x;
    if (i < NN) {
        int v = g_rowptr[i] + g_bsums[i >> 10];
        g_rowptr[i] = v;
        g_cursor[i] = v;
    }
    if (i == 0) g_rowptr[NN] = EE;
}

__global__ void k_fill(const int* __restrict__ ei) {
    int e = blockIdx.x * blockDim.x + threadIdx.x;
    if (e < EE) {
        int src = ei[e];
        int dst = ei[EE + e];
        int pos = atomicAdd(&g_cursor[dst], 1);
        g_colb[pos] = src << 8;      // byte offset: src * 256
        g_dstp[pos] = dst;
    }
}

// ---------------- edge-weight pre-pass (per layer), fp16 output ----------------
__global__ __launch_bounds__(256) void k_ew() {
    int e = blockIdx.x * blockDim.x + threadIdx.x;
    if (e >= EE) return;
    int off = g_colb[e];                               // s << 8
    int d = g_dstp[e];
    const float4 a = *(const float4*)((const char*)g_asrc + (off >> 4));  // s*16 bytes
    const float4 ad = *(const float4*)&g_adst[d * 4];
    float w0 = __expf(lrelu(a.x + ad.x));
    float w1 = __expf(lrelu(a.y + ad.y));
    float w2 = __expf(lrelu(a.z + ad.z));
    float w3 = __expf(lrelu(a.w + ad.w));
    __half2 p01 = __floats2half2_rn(w0, w1);
    __half2 p23 = __floats2half2_rn(w2, w3);
    uint2 o;
    o.x = *(uint32_t*)&p01;
    o.y = *(uint32_t*)&p23;
    *(uint2*)&g_ewh[(size_t)e * 4] = o;
}

// ---------------- layer-0 GEMM [NN,7]@[7,128] + fused alpha ----------------
__global__ __launch_bounds__(128) void k_gemm0(const float* __restrict__ x,
                                               const float* __restrict__ W,
                                               const float* __restrict__ aws,
                                               const float* __restrict__ awd,
                                               __half* __restrict__ outh) {
    __shared__ float Ws[7 * 128];
    __shared__ float xs[8 * 7];
    int t = threadIdx.x;
    int w = t >> 5, lane = t & 31;
    for (int i = t; i < 7 * 128; i += 128) Ws[i] = W[i];
    int base = blockIdx.x * 8;
    for (int i = t; i < 8 * 7; i += 128) {
        int nn = base + i / 7;
        xs[i] = (nn < NN) ? x[nn * 7 + (i % 7)] : 0.f;
    }
    float awsv = aws[t], awdv = awd[t];
    __syncthreads();
    for (int j = 0; j < 8; j++) {
        int n = base + j;
        if (n < NN) {
            float s = 0.f;
#pragma unroll
            for (int k = 0; k < 7; k++) s = fmaf(xs[j * 7 + k], Ws[k * 128 + t], s);
            outh[(size_t)n * DD + t] = __float2half(s);
            float ps = s * awsv, pd = s * awdv;
#pragma unroll
            for (int o = 16; o >= 1; o >>= 1) {
                ps += __shfl_xor_sync(0xffffffffu, ps, o);
                pd += __shfl_xor_sync(0xffffffffu, pd, o);
            }
            if (lane == 0) {
                g_asrc[n * 4 + w] = ps;
                g_adst[n * 4 + w] = pd;
            }
        }
    }
}

// ---------------- layers 1-3 GEMM: wmma fp16 split + fused alpha, fp16 output
#define BSTRIDE 136
#define ASTRIDE 40
#define SMEM_TC2 91136

__global__ __launch_bounds__(256, 2)
void k_gemm_tc(const __half* __restrict__ Ahi, const __half* __restrict__ Alo,
               const __half* __restrict__ Whi, const __half* __restrict__ Wlo,
               __half* __restrict__ Couth,
               const float* __restrict__ aw_src, const float* __restrict__ aw_dst) {
    extern __shared__ char dsm[];
    float* awsS = (float*)dsm;
    float* awdS = (float*)(dsm + 512);
    __half* Bh = (__half*)(dsm + 1024);
    __half* Bl = (__half*)(dsm + 35840);
    __half* Ah = (__half*)(dsm + 70656);
    __half* Al = (__half*)(dsm + 80896);
    const int tid = threadIdx.x;
    const int wid = tid >> 5;
    const int lane = tid & 31;
    const int row0 = blockIdx.x * 128;
    const int warp_m = wid & 3;
    const int warp_n = wid >> 2;

    if (tid < 128) {
        awsS[tid] = aw_src[tid];
        awdS[tid] = aw_dst[tid];
    }
    {
        int br = tid >> 1, cb = (tid & 1) * 64;
        const uint4* sh = (const uint4*)&Whi[br * DD + cb];
        const uint4* sl = (const uint4*)&Wlo[br * DD + cb];
        uint4* dh = (uint4*)&Bh[br * BSTRIDE + cb];
        uint4* dl = (uint4*)&Bl[br * BSTRIDE + cb];
#pragma unroll
        for (int i = 0; i < 8; i++) { dh[i] = sh[i]; dl[i] = sl[i]; }
    }
    const int ar = tid >> 1;
    const int akb = (tid & 1) * 16;
    const size_t agrow = (size_t)min(row0 + ar, NN - 1) * DD;
#define LOAD_A(c)                                                             \
    do {                                                                      \
        const uint4* sh_ = (const uint4*)&Ahi[agrow + (c) * 32 + akb];        \
        const uint4* sl_ = (const uint4*)&Alo[agrow + (c) * 32 + akb];        \
        uint4* dh_ = (uint4*)&Ah[ar * ASTRIDE + akb];                         \
        uint4* dl_ = (uint4*)&Al[ar * ASTRIDE + akb];                         \
        dh_[0] = sh_[0]; dh_[1] = sh_[1];                                     \
        dl_[0] = sl_[0]; dl_[1] = sl_[1];                                     \
    } while (0)

    wmma::fragment<wmma::accumulator, 16, 16, 16, float> acc[2][4];
#pragma unroll
    for (int im = 0; im < 2; im++)
#pragma unroll
        for (int in = 0; in < 4; in++) wmma::fill_fragment(acc[im][in], 0.f);

    LOAD_A(0);
    __syncthreads();

#pragma unroll
    for (int c = 0; c < 4; c++) {
#pragma unroll
        for (int ksl = 0; ksl < 2; ksl++) {
            wmma::fragment<wmma::matrix_a, 16, 16, 16, __half, wmma::row_major> ah[2], al[2];
#pragma unroll
            for (int im = 0; im < 2; im++) {
                wmma::load_matrix_sync(ah[im], &Ah[(warp_m * 32 + im * 16) * ASTRIDE + ksl * 16], ASTRIDE);
                wmma::load_matrix_sync(al[im], &Al[(warp_m * 32 + im * 16) * ASTRIDE + ksl * 16], ASTRIDE);
            }
            const int krow = c * 32 + ksl * 16;
#pragma unroll
            for (int in = 0; in < 4; in++) {
                wmma::fragment<wmma::matrix_b, 16, 16, 16, __half, wmma::row_major> bh, bl;
                wmma::load_matrix_sync(bh, &Bh[krow * BSTRIDE + warp_n * 64 + in * 16], BSTRIDE);
                wmma::load_matrix_sync(bl, &Bl[krow * BSTRIDE + warp_n * 64 + in * 16], BSTRIDE);
#pragma unroll
                for (int im = 0; im < 2; im++) {
                    wmma::mma_sync(acc[im][in], ah[im], bh, acc[im][in]);
                    wmma::mma_sync(acc[im][in], al[im], bh, acc[im][in]);
                    wmma::mma_sync(acc[im][in], ah[im], bl, acc[im][in]);
                }
            }
        }
        __syncthreads();
        if (c < 3) {
            LOAD_A(c + 1);
            __syncthreads();
        }
    }

    float* osm = (float*)(dsm + 1024);
#pragma unroll
    for (int im = 0; im < 2; im++)
#pragma unroll
        for (int in = 0; in < 4; in++)
            wmma::store_matrix_sync(&osm[(warp_m * 32 + im * 16) * BSTRIDE + warp_n * 64 + in * 16],
                                    acc[im][in], BSTRIDE, wmma::mem_row_major);
    __syncthreads();

    if (wid < 4) {
        int r = wid * 32 + lane;
        int grow = row0 + r;
        if (grow < NN) {
#pragma unroll
            for (int b = 0; b < 4; b++) {
                float asum = 0.f, dsum = 0.f;
#pragma unroll
                for (int i = 0; i < 32; i++) {
                    float v = osm[r * BSTRIDE + b * 32 + i];
                    asum = fmaf(v, awsS[b * 32 + i], asum);
                    dsum = fmaf(v, awdS[b * 32 + i], dsum);
                }
                g_asrc[grow * 4 + b] = asum;
                g_adst[grow * 4 + b] = dsum;
            }
        }
    }
    for (int idx = tid; idx < 128 * 32; idx += 256) {
        int r = idx >> 5;
        int c4 = (idx & 31) << 2;
        if (row0 + r < NN) {
            float4 v = *(const float4*)&osm[r * BSTRIDE + c4];
            __half2 h0 = __floats2half2_rn(v.x, v.y);
            __half2 h1 = __floats2half2_rn(v.z, v.w);
            uint2 o;
            o.x = *(uint32_t*)&h0;
            o.y = *(uint32_t*)&h1;
            *(uint2*)&Couth[(size_t)(row0 + r) * DD + c4] = o;
        }
    }
#undef LOAD_A
}

// ---------------- fused GAT aggregate layer -----------------------------
// Node state read/written as fp16 hi/lo pairs; fp32 out written only on final layer.
__global__ __launch_bounds__(256) void k_gat(const __half* __restrict__ hlin,
                                             const __half* __restrict__ phi,
                                             const __half* __restrict__ plo,
                                             const float* __restrict__ bias,
                                             const float* __restrict__ gam,
                                             const float* __restrict__ bet,
                                             float* __restrict__ outp,
                                             __half* __restrict__ ohi,
                                             __half* __restrict__ olo,
                                             int residual, int wbf, int wf32) {
    int n = (blockIdx.x * blockDim.x + threadIdx.x) >> 5;
    if (n >= NN) return;
    const int lane = threadIdx.x & 31;
    const int hd = lane >> 3;
    const int rs = g_rowptr[n], re = g_rowptr[n + 1];

    float4 ad4 = *(const float4*)&g_adst[n * 4];
    float4 as4 = *(const float4*)&g_asrc[n * 4];

    float wslf;
    {
        float lx = (hd == 0) ? (as4.x + ad4.x) : (hd == 1) ? (as4.y + ad4.y)
                 : (hd == 2) ? (as4.z + ad4.z) : (as4.w + ad4.w);
        wslf = __expf(lrelu(lx));
    }
    float z = wslf;

    const char* hb = (const char*)hlin + lane * 8;   // lane-offset base
    uint2 sp = *(const uint2*)(hb + (size_t)n * 256);
    float2 sf01 = __half22float2(*(__half2*)&sp.x);
    float2 sf23 = __half22float2(*(__half2*)&sp.y);
    float a0 = sf01.x * wslf, a1 = sf01.y * wslf, a2 = sf23.x * wslf, a3 = sf23.y * wslf;

    const __half* ewp = g_ewh + hd;                  // per-head weight base

#pragma unroll 8
    for (int e = rs; e < re; e++) {
        int off = __ldg(&g_colb[e]);                 // uniform broadcast (L1)
        float wj = __half2float(__ldg(&ewp[(size_t)e * 4]));
        uint2 p = *(const uint2*)(hb + off);
        float2 f01 = __half22float2(*(__half2*)&p.x);
        float2 f23 = __half22float2(*(__half2*)&p.y);
        a0 = fmaf(f01.x, wj, a0);
        a1 = fmaf(f01.y, wj, a1);
        a2 = fmaf(f23.x, wj, a2);
        a3 = fmaf(f23.y, wj, a3);
        z += wj;
    }
    float invz = 1.f / (z + 1e-16f);
    a0 *= invz; a1 *= invz; a2 *= invz; a3 *= invz;

    float4 bv = *(const float4*)&bias[lane * 4];
    a0 += bv.x; a1 += bv.y; a2 += bv.z; a3 += bv.w;
    float sm = a0 + a1 + a2 + a3;
#pragma unroll
    for (int o = 16; o >= 1; o >>= 1) sm += __shfl_xor_sync(0xffffffffu, sm, o);
    float mean = sm * (1.f / DD);
    float d0 = a0 - mean, d1 = a1 - mean, d2 = a2 - mean, d3 = a3 - mean;
    float sq = d0 * d0 + d1 * d1 + d2 * d2 + d3 * d3;
#pragma unroll
    for (int o = 16; o >= 1; o >>= 1) sq += __shfl_xor_sync(0xffffffffu, sq, o);
    float rstd = rsqrtf(sq * (1.f / DD) + 1e-5f);
    float4 gv = *(const float4*)&gam[lane * 4];
    float4 bev = *(const float4*)&bet[lane * 4];
    float v0 = d0 * rstd * gv.x + bev.x;
    float v1 = d1 * rstd * gv.y + bev.y;
    float v2 = d2 * rstd * gv.z + bev.z;
    float v3 = d3 * rstd * gv.w + bev.w;
    v0 = v0 > 0.f ? v0 : __expf(v0) - 1.f;
    v1 = v1 > 0.f ? v1 : __expf(v1) - 1.f;
    v2 = v2 > 0.f ? v2 : __expf(v2) - 1.f;
    v3 = v3 > 0.f ? v3 : __expf(v3) - 1.f;
    if (residual) {
        // hprev = hi + lo (exact to 2^-22)
        uint2 ph = *(const uint2*)&phi[(size_t)n * DD + lane * 4];
        uint2 pl = *(const uint2*)&plo[(size_t)n * DD + lane * 4];
        float2 h01 = __half22float2(*(__half2*)&ph.x);
        float2 h23 = __half22float2(*(__half2*)&ph.y);
        float2 l01 = __half22float2(*(__half2*)&pl.x);
        float2 l23 = __half22float2(*(__half2*)&pl.y);
        v0 += h01.x + l01.x;
        v1 += h01.y + l01.y;
        v2 += h23.x + l23.x;
        v3 += h23.y + l23.y;
    }
    if (wf32) {
        *(float4*)&outp[(size_t)n * DD + lane * 4] = make_float4(v0, v1, v2, v3);
    }
    if (wbf) {
        __half h0 = __float2half(v0);
        __half h1 = __float2half(v1);
        __half h2 = __float2half(v2);
        __half h3 = __float2half(v3);
        __half l0 = __float2half(v0 - __half2float(h0));
        __half l1 = __float2half(v1 - __half2float(h1));
        __half l2 = __float2half(v2 - __half2float(h2));
        __half l3 = __float2half(v3 - __half2float(h3));
        uint2 ph, pl;
        ph.x = (uint32_t)__half_as_ushort(h0) | ((uint32_t)__half_as_ushort(h1) << 16);
        ph.y = (uint32_t)__half_as_ushort(h2) | ((uint32_t)__half_as_ushort(h3) << 16);
        pl.x = (uint32_t)__half_as_ushort(l0) | ((uint32_t)__half_as_ushort(l1) << 16);
        pl.y = (uint32_t)__half_as_ushort(l2) | ((uint32_t)__half_as_ushort(l3) << 16);
        *(uint2*)&ohi[(size_t)n * DD + lane * 4] = ph;
        *(uint2*)&olo[(size_t)n * DD + lane * 4] = pl;
    }
}

// ---------------- graph pooling ----------------
__global__ __launch_bounds__(128) void k_pool(const float* __restrict__ ne,
                                              const int* __restrict__ batch,
                                              float* __restrict__ gout) {
    int base = blockIdx.x * 128;
    if (base >= NN) return;
    int d = threadIdx.x;
    int end = base + 128;
    if (end > NN) end = NN;
    float acc = 0.f;
    int cg = __ldg(&batch[base]);
    for (int n = base; n < end; n++) {
        int gidx = __ldg(&batch[n]);
        if (gidx != cg) {
            atomicAdd(&gout[cg * DD + d], acc);
            acc = 0.f;
            cg = gidx;
        }
        acc += ne[(size_t)n * DD + d];
    }
    atomicAdd(&gout[cg * DD + d], acc);
}

// per-graph counts via binary search on sorted batch
__global__ void k_final(float* __restrict__ gout, const int* __restrict__ batch) {
    int g = blockIdx.x;
    int d = threadIdx.x;
    __shared__ int cnt_s;
    if (d == 0) {
        int lo = 0, hi = NN;
        while (lo < hi) { int m = (lo + hi) >> 1; if (batch[m] < g) lo = m + 1; else hi = m; }
        int lb = lo;
        lo = lb; hi = NN;
        while (lo < hi) { int m = (lo + hi) >> 1; if (batch[m] < g + 1) lo = m + 1; else hi = m; }
        cnt_s = lo - lb;
    }
    __syncthreads();
    gout[g * DD + d] /= fmaxf((float)cnt_s, 1.f);
}

// ---------------- host launch ----------------
extern "C" void kernel_launch(void* const* d_in, const int* in_sizes, int n_in,
                              void* d_out, int out_size) {
    const float* x    = (const float*)d_in[0];
    const int*   ei   = (const int*)d_in[1];
    const int*   batch= (const int*)d_in[2];
    const float* W0   = (const float*)d_in[3];
    const float* as0  = (const float*)d_in[4];
    const float* ad0  = (const float*)d_in[5];
    const float* b0   = (const float*)d_in[6];
    const float* Ws   = (const float*)d_in[7];
    const float* asr  = (const float*)d_in[8];
    const float* ads  = (const float*)d_in[9];
    const float* bs   = (const float*)d_in[10];
    const float* lng  = (const float*)d_in[11];
    const float* lnb  = (const float*)d_in[12];
    float* out  = (float*)d_out;
    float* gout = out + (size_t)NN * DD;

    __half *hXhi, *hXlo, *hYhi, *hYlo, *hlinh, *Whi, *Wlo;
    cudaGetSymbolAddress((void**)&hXhi, g_hXhi);
    cudaGetSymbolAddress((void**)&hXlo, g_hXlo);
    cudaGetSymbolAddress((void**)&hYhi, g_hYhi);
    cudaGetSymbolAddress((void**)&hYlo, g_hYlo);
    cudaGetSymbolAddress((void**)&hlinh, g_hlinh);
    cudaGetSymbolAddress((void**)&Whi, g_Whi);
    cudaGetSymbolAddress((void**)&Wlo, g_Wlo);

    cudaFuncSetAttribute(k_gemm_tc, cudaFuncAttributeMaxDynamicSharedMemorySize, SMEM_TC2);

    // CSR build + init (parallel 3-kernel scan)
    k_zero<<<(NN + 255) / 256, 256>>>(gout, Ws);
    k_count<<<(EE + 255) / 256, 256>>>(ei);
    k_scan_block<<<NB1, 1024>>>();
    k_scan_bsums<<<1, 128>>>();
    k_scan_add<<<(NN + 255) / 256, 256>>>();
    k_fill<<<(EE + 255) / 256, 256>>>(ei);

    // layer 0: h_0 -> pair X
    k_gemm0<<<(NN + 7) / 8, 128>>>(x, W0, as0, ad0, hlinh);
    k_ew<<<(EE + 255) / 256, 256>>>();
    k_gat<<<(NN * 32 + 255) / 256, 256>>>(hlinh, nullptr, nullptr, b0, lng, lnb,
                                          nullptr, hXhi, hXlo, 0, 1, 0);

    // layer 1: reads X, writes Y
    k_gemm_tc<<<(NN + 127) / 128, 256, SMEM_TC2>>>(hXhi, hXlo, Whi, Wlo, hlinh, asr, ads);
    k_ew<<<(EE + 255) / 256, 256>>>();
    k_gat<<<(NN * 32 + 255) / 256, 256>>>(hlinh, hXhi, hXlo, bs, lng + DD, lnb + DD,
                                          nullptr, hYhi, hYlo, 1, 1, 0);

    // layer 2: reads Y, writes X
    k_gemm_tc<<<(NN + 127) / 128, 256, SMEM_TC2>>>(hYhi, hYlo, Whi + DD * DD, Wlo + DD * DD,
                                                   hlinh, asr + DD, ads + DD);
    k_ew<<<(EE + 255) / 256, 256>>>();
    k_gat<<<(NN * 32 + 255) / 256, 256>>>(hlinh, hYhi, hYlo, bs + DD, lng + 2 * DD, lnb + 2 * DD,
                                          nullptr, hXhi, hXlo, 1, 1, 0);

    // layer 3: reads X, writes fp32 out
    k_gemm_tc<<<(NN + 127) / 128, 256, SMEM_TC2>>>(hXhi, hXlo, Whi + 2 * DD * DD, Wlo + 2 * DD * DD,
                                                   hlinh, asr + 2 * DD, ads + 2 * DD);
    k_ew<<<(EE + 255) / 256, 256>>>();
    k_gat<<<(NN * 32 + 255) / 256, 256>>>(hlinh, hXhi, hXlo, bs + 2 * DD, lng + 3 * DD, lnb + 3 * DD,
                                          out, nullptr, nullptr, 1, 0, 1);

    // graph mean pooling
    k_pool<<<(NN + 127) / 128, 128>>>(out, batch, gout);
    k_final<<<GG, 128>>>(gout, batch);
}

// round 16
// speedup vs baseline: 2.2008x; 1.0415x over previous
#include <cuda_runtime.h>
#include <cuda_fp16.h>
#include <cstdint>
#include <mma.h>

#define NN 100000
#define EE 1600000
#define HH 4
#define CC 32
#define DD 128
#define GG 64
#define NEG 0.2f
#define NB1 ((NN + 1023) / 1024)

using namespace nvcuda;

// ---------------- device scratch ----------------
// node state h stored as fp16 hi/lo pairs (h = hi + lo, exact to 2^-22)
__device__ __half g_hXhi[(size_t)NN * DD];
__device__ __half g_hXlo[(size_t)NN * DD];
__device__ __half g_hYhi[(size_t)NN * DD];
__device__ __half g_hYlo[(size_t)NN * DD];
__device__ __half g_hlinh[(size_t)NN * DD];      // fp16 hlin (gather operand)
__device__ __half g_Whi[3 * DD * DD];
__device__ __half g_Wlo[3 * DD * DD];
__device__ float g_asrc[NN * HH];
__device__ float g_adst[NN * HH];
__device__ __half g_ewh[(size_t)EE * 4];         // per-edge softmax weights, fp16
__device__ int   g_deg[NN];
__device__ int   g_rowptr[NN + 1];
__device__ int   g_cursor[NN];
__device__ int   g_colb[EE];                     // src << 8 (byte offset into hlin)
__device__ int   g_dstp[EE];                     // dst per CSR slot
__device__ int   g_bsums[128];

__device__ __forceinline__ float lrelu(float x) { return x > 0.f ? x : NEG * x; }

// ---------------- init (zero + W fp16-split fused) ----------------
__global__ void k_zero(float* __restrict__ gout, const float* __restrict__ Ws) {
    int i = blockIdx.x * blockDim.x + threadIdx.x;
    if (i < NN) g_deg[i] = 0;
    if (i < GG * DD) gout[i] = 0.f;
    if (i < 3 * DD * DD) {
        float f = Ws[i];
        __half hi = __float2half(f);
        g_Whi[i] = hi;
        g_Wlo[i] = __float2half(f - __half2float(hi));
    }
}

__global__ void k_count(const int* __restrict__ ei) {
    int e = blockIdx.x * blockDim.x + threadIdx.x;
    if (e < EE) atomicAdd(&g_deg[ei[EE + e]], 1);
}

__global__ void k_scan_block() {
    __shared__ int s[1024];
    int i = blockIdx.x * 1024 + threadIdx.x;
    int v = (i < NN) ? g_deg[i] : 0;
    s[threadIdx.x] = v;
    __syncthreads();
    for (int off = 1; off < 1024; off <<= 1) {
        int t = (threadIdx.x >= off) ? s[threadIdx.x - off] : 0;
        __syncthreads();
        s[threadIdx.x] += t;
        __syncthreads();
    }
    if (i < NN) g_rowptr[i] = s[threadIdx.x] - v;
    if (threadIdx.x == 1023) g_bsums[blockIdx.x] = s[1023];
}

__global__ void k_scan_bsums() {
    __shared__ int s[128];
    int t = threadIdx.x;
    int v = (t < NB1) ? g_bsums[t] : 0;
    s[t] = v;
    __syncthreads();
    for (int off = 1; off < 128; off <<= 1) {
        int u = (t >= off) ? s[t - off] : 0;
        __syncthreads();
        s[t] += u;
        __syncthreads();
    }
    if (t < NB1) g_bsums[t] = s[t] - v;
}

__global__ void k_scan_add() {
    int i = blockIdx.x * blockDim.x + threadIdx.x;
    if (i < NN) {
        int v = g_rowptr[i] + g_bsums[i >> 10];
        g_rowptr[i] = v;
        g_cursor[i] = v;
    }
    if (i == 0) g_rowptr[NN] = EE;
}

__global__ void k_fill(const int* __restrict__ ei) {
    int e = blockIdx.x * blockDim.x + threadIdx.x;
    if (e < EE) {
        int src = ei[e];
        int dst = ei[EE + e];
        int pos = atomicAdd(&g_cursor[dst], 1);
        g_colb[pos] = src << 8;      // byte offset: src * 256
        g_dstp[pos] = dst;
    }
}

// ---------------- edge-weight pre-pass (per layer), fp16 output ----------------
__global__ __launch_bounds__(256) void k_ew() {
    int e = blockIdx.x * blockDim.x + threadIdx.x;
    if (e >= EE) return;
    int off = g_colb[e];                               // s << 8
    int d = g_dstp[e];
    const float4 a = *(const float4*)((const char*)g_asrc + (off >> 4));  // s*16 bytes
    const float4 ad = *(const float4*)&g_adst[d * 4];
    float w0 = __expf(lrelu(a.x + ad.x));
    float w1 = __expf(lrelu(a.y + ad.y));
    float w2 = __expf(lrelu(a.z + ad.z));
    float w3 = __expf(lrelu(a.w + ad.w));
    __half2 p01 = __floats2half2_rn(w0, w1);
    __half2 p23 = __floats2half2_rn(w2, w3);
    uint2 o;
    o.x = *(uint32_t*)&p01;
    o.y = *(uint32_t*)&p23;
    *(uint2*)&g_ewh[(size_t)e * 4] = o;
}

// ---------------- layer-0 GEMM [NN,7]@[7,128] + fused alpha ----------------
__global__ __launch_bounds__(128) void k_gemm0(const float* __restrict__ x,
                                               const float* __restrict__ W,
                                               const float* __restrict__ aws,
                                               const float* __restrict__ awd,
                                               __half* __restrict__ outh) {
    __shared__ float Ws[7 * 128];
    __shared__ float xs[8 * 7];
    int t = threadIdx.x;
    int w = t >> 5, lane = t & 31;
    for (int i = t; i < 7 * 128; i += 128) Ws[i] = W[i];
    int base = blockIdx.x * 8;
    for (int i = t; i < 8 * 7; i += 128) {
        int nn = base + i / 7;
        xs[i] = (nn < NN) ? x[nn * 7 + (i % 7)] : 0.f;
    }
    float awsv = aws[t], awdv = awd[t];
    __syncthreads();
    for (int j = 0; j < 8; j++) {
        int n = base + j;
        if (n < NN) {
            float s = 0.f;
#pragma unroll
            for (int k = 0; k < 7; k++) s = fmaf(xs[j * 7 + k], Ws[k * 128 + t], s);
            outh[(size_t)n * DD + t] = __float2half(s);
            float ps = s * awsv, pd = s * awdv;
#pragma unroll
            for (int o = 16; o >= 1; o >>= 1) {
                ps += __shfl_xor_sync(0xffffffffu, ps, o);
                pd += __shfl_xor_sync(0xffffffffu, pd, o);
            }
            if (lane == 0) {
                g_asrc[n * 4 + w] = ps;
                g_adst[n * 4 + w] = pd;
            }
        }
    }
}

// ---------------- layers 1-3 GEMM: A fp16 (hi only), W fp16-split, fused alpha
#define BSTRIDE 136
#define ASTRIDE 40
#define SMEM_TC2 81152   // aws 512 | awd 512 | Bh 34816 | Bl 34816 | Ah 10240 | (osm reuses Bh/Bl)

__global__ __launch_bounds__(256, 2)
void k_gemm_tc(const __half* __restrict__ Ahi,
               const __half* __restrict__ Whi, const __half* __restrict__ Wlo,
               __half* __restrict__ Couth,
               const float* __restrict__ aw_src, const float* __restrict__ aw_dst) {
    extern __shared__ char dsm[];
    float* awsS = (float*)dsm;
    float* awdS = (float*)(dsm + 512);
    __half* Bh = (__half*)(dsm + 1024);
    __half* Bl = (__half*)(dsm + 35840);
    __half* Ah = (__half*)(dsm + 70656);
    const int tid = threadIdx.x;
    const int wid = tid >> 5;
    const int lane = tid & 31;
    const int row0 = blockIdx.x * 128;
    const int warp_m = wid & 3;
    const int warp_n = wid >> 2;

    if (tid < 128) {
        awsS[tid] = aw_src[tid];
        awdS[tid] = aw_dst[tid];
    }
    {
        int br = tid >> 1, cb = (tid & 1) * 64;
        const uint4* sh = (const uint4*)&Whi[br * DD + cb];
        const uint4* sl = (const uint4*)&Wlo[br * DD + cb];
        uint4* dh = (uint4*)&Bh[br * BSTRIDE + cb];
        uint4* dl = (uint4*)&Bl[br * BSTRIDE + cb];
#pragma unroll
        for (int i = 0; i < 8; i++) { dh[i] = sh[i]; dl[i] = sl[i]; }
    }
    const int ar = tid >> 1;
    const int akb = (tid & 1) * 16;
    const size_t agrow = (size_t)min(row0 + ar, NN - 1) * DD;
#define LOAD_A(c)                                                             \
    do {                                                                      \
        const uint4* sh_ = (const uint4*)&Ahi[agrow + (c) * 32 + akb];        \
        uint4* dh_ = (uint4*)&Ah[ar * ASTRIDE + akb];                         \
        dh_[0] = sh_[0]; dh_[1] = sh_[1];                                     \
    } while (0)

    wmma::fragment<wmma::accumulator, 16, 16, 16, float> acc[2][4];
#pragma unroll
    for (int im = 0; im < 2; im++)
#pragma unroll
        for (int in = 0; in < 4; in++) wmma::fill_fragment(acc[im][in], 0.f);

    LOAD_A(0);
    __syncthreads();

#pragma unroll
    for (int c = 0; c < 4; c++) {
#pragma unroll
        for (int ksl = 0; ksl < 2; ksl++) {
            wmma::fragment<wmma::matrix_a, 16, 16, 16, __half, wmma::row_major> ah[2];
#pragma unroll
            for (int im = 0; im < 2; im++)
                wmma::load_matrix_sync(ah[im], &Ah[(warp_m * 32 + im * 16) * ASTRIDE + ksl * 16], ASTRIDE);
            const int krow = c * 32 + ksl * 16;
#pragma unroll
            for (int in = 0; in < 4; in++) {
                wmma::fragment<wmma::matrix_b, 16, 16, 16, __half, wmma::row_major> bh, bl;
                wmma::load_matrix_sync(bh, &Bh[krow * BSTRIDE + warp_n * 64 + in * 16], BSTRIDE);
                wmma::load_matrix_sync(bl, &Bl[krow * BSTRIDE + warp_n * 64 + in * 16], BSTRIDE);
#pragma unroll
                for (int im = 0; im < 2; im++) {
                    wmma::mma_sync(acc[im][in], ah[im], bh, acc[im][in]);
                    wmma::mma_sync(acc[im][in], ah[im], bl, acc[im][in]);
                }
            }
        }
        __syncthreads();
        if (c < 3) {
            LOAD_A(c + 1);
            __syncthreads();
        }
    }

    float* osm = (float*)(dsm + 1024);
#pragma unroll
    for (int im = 0; im < 2; im++)
#pragma unroll
        for (int in = 0; in < 4; in++)
            wmma::store_matrix_sync(&osm[(warp_m * 32 + im * 16) * BSTRIDE + warp_n * 64 + in * 16],
                                    acc[im][in], BSTRIDE, wmma::mem_row_major);
    __syncthreads();

    if (wid < 4) {
        int r = wid * 32 + lane;
        int grow = row0 + r;
        if (grow < NN) {
#pragma unroll
            for (int b = 0; b < 4; b++) {
                float asum = 0.f, dsum = 0.f;
#pragma unroll
                for (int i = 0; i < 32; i++) {
                    float v = osm[r * BSTRIDE + b * 32 + i];
                    asum = fmaf(v, awsS[b * 32 + i], asum);
                    dsum = fmaf(v, awdS[b * 32 + i], dsum);
                }
                g_asrc[grow * 4 + b] = asum;
                g_adst[grow * 4 + b] = dsum;
            }
        }
    }
    for (int idx = tid; idx < 128 * 32; idx += 256) {
        int r = idx >> 5;
        int c4 = (idx & 31) << 2;
        if (row0 + r < NN) {
            float4 v = *(const float4*)&osm[r * BSTRIDE + c4];
            __half2 h0 = __floats2half2_rn(v.x, v.y);
            __half2 h1 = __floats2half2_rn(v.z, v.w);
            uint2 o;
            o.x = *(uint32_t*)&h0;
            o.y = *(uint32_t*)&h1;
            *(uint2*)&Couth[(size_t)(row0 + r) * DD + c4] = o;
        }
    }
#undef LOAD_A
}

// ---------------- fused GAT aggregate layer -----------------------------
__global__ __launch_bounds__(256) void k_gat(const __half* __restrict__ hlin,
                                             const __half* __restrict__ phi,
                                             const __half* __restrict__ plo,
                                             const float* __restrict__ bias,
                                             const float* __restrict__ gam,
                                             const float* __restrict__ bet,
                                             float* __restrict__ outp,
                                             __half* __restrict__ ohi,
                                             __half* __restrict__ olo,
                                             int residual, int wbf, int wf32) {
    int n = (blockIdx.x * blockDim.x + threadIdx.x) >> 5;
    if (n >= NN) return;
    const int lane = threadIdx.x & 31;
    const int hd = lane >> 3;
    const int rs = g_rowptr[n], re = g_rowptr[n + 1];

    float4 ad4 = *(const float4*)&g_adst[n * 4];
    float4 as4 = *(const float4*)&g_asrc[n * 4];

    float wslf;
    {
        float lx = (hd == 0) ? (as4.x + ad4.x) : (hd == 1) ? (as4.y + ad4.y)
                 : (hd == 2) ? (as4.z + ad4.z) : (as4.w + ad4.w);
        wslf = __expf(lrelu(lx));
    }
    float z = wslf;

    const char* hb = (const char*)hlin + lane * 8;   // lane-offset base
    uint2 sp = *(const uint2*)(hb + (size_t)n * 256);
    float2 sf01 = __half22float2(*(__half2*)&sp.x);
    float2 sf23 = __half22float2(*(__half2*)&sp.y);
    float a0 = sf01.x * wslf, a1 = sf01.y * wslf, a2 = sf23.x * wslf, a3 = sf23.y * wslf;

    const __half* ewp = g_ewh + hd;                  // per-head weight base

#pragma unroll 8
    for (int e = rs; e < re; e++) {
        int off = __ldg(&g_colb[e]);                 // uniform broadcast (L1)
        float wj = __half2float(__ldg(&ewp[(size_t)e * 4]));
        uint2 p = *(const uint2*)(hb + off);
        float2 f01 = __half22float2(*(__half2*)&p.x);
        float2 f23 = __half22float2(*(__half2*)&p.y);
        a0 = fmaf(f01.x, wj, a0);
        a1 = fmaf(f01.y, wj, a1);
        a2 = fmaf(f23.x, wj, a2);
        a3 = fmaf(f23.y, wj, a3);
        z += wj;
    }
    float invz = 1.f / (z + 1e-16f);
    a0 *= invz; a1 *= invz; a2 *= invz; a3 *= invz;

    float4 bv = *(const float4*)&bias[lane * 4];
    a0 += bv.x; a1 += bv.y; a2 += bv.z; a3 += bv.w;
    float sm = a0 + a1 + a2 + a3;
#pragma unroll
    for (int o = 16; o >= 1; o >>= 1) sm += __shfl_xor_sync(0xffffffffu, sm, o);
    float mean = sm * (1.f / DD);
    float d0 = a0 - mean, d1 = a1 - mean, d2 = a2 - mean, d3 = a3 - mean;
    float sq = d0 * d0 + d1 * d1 + d2 * d2 + d3 * d3;
#pragma unroll
    for (int o = 16; o >= 1; o >>= 1) sq += __shfl_xor_sync(0xffffffffu, sq, o);
    float rstd = rsqrtf(sq * (1.f / DD) + 1e-5f);
    float4 gv = *(const float4*)&gam[lane * 4];
    float4 bev = *(const float4*)&bet[lane * 4];
    float v0 = d0 * rstd * gv.x + bev.x;
    float v1 = d1 * rstd * gv.y + bev.y;
    float v2 = d2 * rstd * gv.z + bev.z;
    float v3 = d3 * rstd * gv.w + bev.w;
    v0 = v0 > 0.f ? v0 : __expf(v0) - 1.f;
    v1 = v1 > 0.f ? v1 : __expf(v1) - 1.f;
    v2 = v2 > 0.f ? v2 : __expf(v2) - 1.f;
    v3 = v3 > 0.f ? v3 : __expf(v3) - 1.f;
    if (residual) {
        uint2 ph = *(const uint2*)&phi[(size_t)n * DD + lane * 4];
        uint2 pl = *(const uint2*)&plo[(size_t)n * DD + lane * 4];
        float2 h01 = __half22float2(*(__half2*)&ph.x);
        float2 h23 = __half22float2(*(__half2*)&ph.y);
        float2 l01 = __half22float2(*(__half2*)&pl.x);
        float2 l23 = __half22float2(*(__half2*)&pl.y);
        v0 += h01.x + l01.x;
        v1 += h01.y + l01.y;
        v2 += h23.x + l23.x;
        v3 += h23.y + l23.y;
    }
    if (wf32) {
        *(float4*)&outp[(size_t)n * DD + lane * 4] = make_float4(v0, v1, v2, v3);
    }
    if (wbf) {
        __half h0 = __float2half(v0);
        __half h1 = __float2half(v1);
        __half h2 = __float2half(v2);
        __half h3 = __float2half(v3);
        __half l0 = __float2half(v0 - __half2float(h0));
        __half l1 = __float2half(v1 - __half2float(h1));
        __half l2 = __float2half(v2 - __half2float(h2));
        __half l3 = __float2half(v3 - __half2float(h3));
        uint2 ph, pl;
        ph.x = (uint32_t)__half_as_ushort(h0) | ((uint32_t)__half_as_ushort(h1) << 16);
        ph.y = (uint32_t)__half_as_ushort(h2) | ((uint32_t)__half_as_ushort(h3) << 16);
        pl.x = (uint32_t)__half_as_ushort(l0) | ((uint32_t)__half_as_ushort(l1) << 16);
        pl.y = (uint32_t)__half_as_ushort(l2) | ((uint32_t)__half_as_ushort(l3) << 16);
        *(uint2*)&ohi[(size_t)n * DD + lane * 4] = ph;
        *(uint2*)&olo[(size_t)n * DD + lane * 4] = pl;
    }
}

// ---------------- graph pooling ----------------
__global__ __launch_bounds__(128) void k_pool(const float* __restrict__ ne,
                                              const int* __restrict__ batch,
                                              float* __restrict__ gout) {
    int base = blockIdx.x * 128;
    if (base >= NN) return;
    int d = threadIdx.x;
    int end = base + 128;
    if (end > NN) end = NN;
    float acc = 0.f;
    int cg = __ldg(&batch[base]);
    for (int n = base; n < end; n++) {
        int gidx = __ldg(&batch[n]);
        if (gidx != cg) {
            atomicAdd(&gout[cg * DD + d], acc);
            acc = 0.f;
            cg = gidx;
        }
        acc += ne[(size_t)n * DD + d];
    }
    atomicAdd(&gout[cg * DD + d], acc);
}

// per-graph counts via binary search on sorted batch
__global__ void k_final(float* __restrict__ gout, const int* __restrict__ batch) {
    int g = blockIdx.x;
    int d = threadIdx.x;
    __shared__ int cnt_s;
    if (d == 0) {
        int lo = 0, hi = NN;
        while (lo < hi) { int m = (lo + hi) >> 1; if (batch[m] < g) lo = m + 1; else hi = m; }
        int lb = lo;
        lo = lb; hi = NN;
        while (lo < hi) { int m = (lo + hi) >> 1; if (batch[m] < g + 1) lo = m + 1; else hi = m; }
        cnt_s = lo - lb;
    }
    __syncthreads();
    gout[g * DD + d] /= fmaxf((float)cnt_s, 1.f);
}

// ---------------- host launch ----------------
extern "C" void kernel_launch(void* const* d_in, const int* in_sizes, int n_in,
                              void* d_out, int out_size) {
    const float* x    = (const float*)d_in[0];
    const int*   ei   = (const int*)d_in[1];
    const int*   batch= (const int*)d_in[2];
    const float* W0   = (const float*)d_in[3];
    const float* as0  = (const float*)d_in[4];
    const float* ad0  = (const float*)d_in[5];
    const float* b0   = (const float*)d_in[6];
    const float* Ws   = (const float*)d_in[7];
    const float* asr  = (const float*)d_in[8];
    const float* ads  = (const float*)d_in[9];
    const float* bs   = (const float*)d_in[10];
    const float* lng  = (const float*)d_in[11];
    const float* lnb  = (const float*)d_in[12];
    float* out  = (float*)d_out;
    float* gout = out + (size_t)NN * DD;

    __half *hXhi, *hXlo, *hYhi, *hYlo, *hlinh, *Whi, *Wlo;
    cudaGetSymbolAddress((void**)&hXhi, g_hXhi);
    cudaGetSymbolAddress((void**)&hXlo, g_hXlo);
    cudaGetSymbolAddress((void**)&hYhi, g_hYhi);
    cudaGetSymbolAddress((void**)&hYlo, g_hYlo);
    cudaGetSymbolAddress((void**)&hlinh, g_hlinh);
    cudaGetSymbolAddress((void**)&Whi, g_Whi);
    cudaGetSymbolAddress((void**)&Wlo, g_Wlo);

    cudaFuncSetAttribute(k_gemm_tc, cudaFuncAttributeMaxDynamicSharedMemorySize, SMEM_TC2);

    // CSR build + init (parallel 3-kernel scan)
    k_zero<<<(NN + 255) / 256, 256>>>(gout, Ws);
    k_count<<<(EE + 255) / 256, 256>>>(ei);
    k_scan_block<<<NB1, 1024>>>();
    k_scan_bsums<<<1, 128>>>();
    k_scan_add<<<(NN + 255) / 256, 256>>>();
    k_fill<<<(EE + 255) / 256, 256>>>(ei);

    // layer 0: h_0 -> pair X
    k_gemm0<<<(NN + 7) / 8, 128>>>(x, W0, as0, ad0, hlinh);
    k_ew<<<(EE + 255) / 256, 256>>>();
    k_gat<<<(NN * 32 + 255) / 256, 256>>>(hlinh, nullptr, nullptr, b0, lng, lnb,
                                          nullptr, hXhi, hXlo, 0, 1, 0);

    // layer 1: reads X(hi), writes Y
    k_gemm_tc<<<(NN + 127) / 128, 256, SMEM_TC2>>>(hXhi, Whi, Wlo, hlinh, asr, ads);
    k_ew<<<(EE + 255) / 256, 256>>>();
    k_gat<<<(NN * 32 + 255) / 256, 256>>>(hlinh, hXhi, hXlo, bs, lng + DD, lnb + DD,
                                          nullptr, hYhi, hYlo, 1, 1, 0);

    // layer 2: reads Y(hi), writes X
    k_gemm_tc<<<(NN + 127) / 128, 256, SMEM_TC2>>>(hYhi, Whi + DD * DD, Wlo + DD * DD,
                                                   hlinh, asr + DD, ads + DD);
    k_ew<<<(EE + 255) / 256, 256>>>();
    k_gat<<<(NN * 32 + 255) / 256, 256>>>(hlinh, hYhi, hYlo, bs + DD, lng + 2 * DD, lnb + 2 * DD,
                                          nullptr, hXhi, hXlo, 1, 1, 0);

    // layer 3: reads X(hi), writes fp32 out
    k_gemm_tc<<<(NN + 127) / 128, 256, SMEM_TC2>>>(hXhi, Whi + 2 * DD * DD, Wlo + 2 * DD * DD,
                                                   hlinh, asr + 2 * DD, ads + 2 * DD);
    k_ew<<<(EE + 255) / 256, 256>>>();
    k_gat<<<(NN * 32 + 255) / 256, 256>>>(hlinh, hXhi, hXlo, bs + 2 * DD, lng + 3 * DD, lnb + 3 * DD,
                                          out, nullptr, nullptr, 1, 0, 1);

    // graph mean pooling
    k_pool<<<(NN + 127) / 128, 128>>>(out, batch, gout);
    k_final<<<GG, 128>>>(gout, batch);
}

// round 17
// speedup vs baseline: 2.3152x; 1.0520x over previous
#include <cuda_runtime.h>
#include <cuda_fp16.h>
#include <cstdint>
#include <mma.h>

#define NN 100000
#define EE 1600000
#define HH 4
#define CC 32
#define DD 128
#define GG 64
#define NEG 0.2f
#define NB1 ((NN + 1023) / 1024)

using namespace nvcuda;

// ---------------- device scratch ----------------
// node state h stored as plain fp16 (residual chain quantized per layer)
__device__ __half g_hX[(size_t)NN * DD];
__device__ __half g_hY[(size_t)NN * DD];
__device__ __half g_hlinh[(size_t)NN * DD];      // fp16 hlin (gather operand)
__device__ __half g_Whi[3 * DD * DD];
__device__ __half g_Wlo[3 * DD * DD];
__device__ float g_asrc[NN * HH];
__device__ float g_adst[NN * HH];
__device__ __half g_ewh[(size_t)EE * 4];         // per-edge softmax weights, fp16
__device__ int   g_deg[NN];
__device__ int   g_rowptr[NN + 1];
__device__ int   g_cursor[NN];
__device__ int   g_colb[EE];                     // src << 8 (byte offset into hlin)
__device__ int   g_dstp[EE];                     // dst per CSR slot
__device__ int   g_bsums[128];

__device__ __forceinline__ float lrelu(float x) { return x > 0.f ? x : NEG * x; }

// ---------------- init (zero + W fp16-split fused) ----------------
__global__ void k_zero(float* __restrict__ gout, const float* __restrict__ Ws) {
    int i = blockIdx.x * blockDim.x + threadIdx.x;
    if (i < NN) g_deg[i] = 0;
    if (i < GG * DD) gout[i] = 0.f;
    if (i < 3 * DD * DD) {
        float f = Ws[i];
        __half hi = __float2half(f);
        g_Whi[i] = hi;
        g_Wlo[i] = __float2half(f - __half2float(hi));
    }
}

__global__ void k_count(const int* __restrict__ ei) {
    int e = blockIdx.x * blockDim.x + threadIdx.x;
    if (e < EE) atomicAdd(&g_deg[ei[EE + e]], 1);
}

__global__ void k_scan_block() {
    __shared__ int s[1024];
    int i = blockIdx.x * 1024 + threadIdx.x;
    int v = (i < NN) ? g_deg[i] : 0;
    s[threadIdx.x] = v;
    __syncthreads();
    for (int off = 1; off < 1024; off <<= 1) {
        int t = (threadIdx.x >= off) ? s[threadIdx.x - off] : 0;
        __syncthreads();
        s[threadIdx.x] += t;
        __syncthreads();
    }
    if (i < NN) g_rowptr[i] = s[threadIdx.x] - v;
    if (threadIdx.x == 1023) g_bsums[blockIdx.x] = s[1023];
}

__global__ void k_scan_bsums() {
    __shared__ int s[128];
    int t = threadIdx.x;
    int v = (t < NB1) ? g_bsums[t] : 0;
    s[t] = v;
    __syncthreads();
    for (int off = 1; off < 128; off <<= 1) {
        int u = (t >= off) ? s[t - off] : 0;
        __syncthreads();
        s[t] += u;
        __syncthreads();
    }
    if (t < NB1) g_bsums[t] = s[t] - v;
}

__global__ void k_scan_add() {
    int i = blockIdx.x * blockDim.x + threadIdx.x;
    if (i < NN) {
        int v = g_rowptr[i] + g_bsums[i >> 10];
        g_rowptr[i] = v;
        g_cursor[i] = v;
    }
    if (i == 0) g_rowptr[NN] = EE;
}

__global__ void k_fill(const int* __restrict__ ei) {
    int e = blockIdx.x * blockDim.x + threadIdx.x;
    if (e < EE) {
        int src = ei[e];
        int dst = ei[EE + e];
        int pos = atomicAdd(&g_cursor[dst], 1);
        g_colb[pos] = src << 8;      // byte offset: src * 256
        g_dstp[pos] = dst;
    }
}

// ---------------- edge-weight pre-pass (per layer), fp16 output ----------------
__global__ __launch_bounds__(256) void k_ew() {
    int e = blockIdx.x * blockDim.x + threadIdx.x;
    if (e >= EE) return;
    int off = g_colb[e];                               // s << 8
    int d = g_dstp[e];
    const float4 a = *(const float4*)((const char*)g_asrc + (off >> 4));  // s*16 bytes
    const float4 ad = *(const float4*)&g_adst[d * 4];
    float w0 = __expf(lrelu(a.x + ad.x));
    float w1 = __expf(lrelu(a.y + ad.y));
    float w2 = __expf(lrelu(a.z + ad.z));
    float w3 = __expf(lrelu(a.w + ad.w));
    __half2 p01 = __floats2half2_rn(w0, w1);
    __half2 p23 = __floats2half2_rn(w2, w3);
    uint2 o;
    o.x = *(uint32_t*)&p01;
    o.y = *(uint32_t*)&p23;
    *(uint2*)&g_ewh[(size_t)e * 4] = o;
}

// ---------------- layer-0 GEMM [NN,7]@[7,128] + fused alpha ----------------
__global__ __launch_bounds__(128) void k_gemm0(const float* __restrict__ x,
                                               const float* __restrict__ W,
                                               const float* __restrict__ aws,
                                               const float* __restrict__ awd,
                                               __half* __restrict__ outh) {
    __shared__ float Ws[7 * 128];
    __shared__ float xs[8 * 7];
    int t = threadIdx.x;
    int w = t >> 5, lane = t & 31;
    for (int i = t; i < 7 * 128; i += 128) Ws[i] = W[i];
    int base = blockIdx.x * 8;
    for (int i = t; i < 8 * 7; i += 128) {
        int nn = base + i / 7;
        xs[i] = (nn < NN) ? x[nn * 7 + (i % 7)] : 0.f;
    }
    float awsv = aws[t], awdv = awd[t];
    __syncthreads();
    for (int j = 0; j < 8; j++) {
        int n = base + j;
        if (n < NN) {
            float s = 0.f;
#pragma unroll
            for (int k = 0; k < 7; k++) s = fmaf(xs[j * 7 + k], Ws[k * 128 + t], s);
            outh[(size_t)n * DD + t] = __float2half(s);
            float ps = s * awsv, pd = s * awdv;
#pragma unroll
            for (int o = 16; o >= 1; o >>= 1) {
                ps += __shfl_xor_sync(0xffffffffu, ps, o);
                pd += __shfl_xor_sync(0xffffffffu, pd, o);
            }
            if (lane == 0) {
                g_asrc[n * 4 + w] = ps;
                g_adst[n * 4 + w] = pd;
            }
        }
    }
}

// ---------------- layers 1-3 GEMM: A fp16, W fp16-split, fused alpha --------
#define BSTRIDE 136
#define ASTRIDE 40
#define SMEM_TC2 81152

__global__ __launch_bounds__(256, 2)
void k_gemm_tc(const __half* __restrict__ Ahi,
               const __half* __restrict__ Whi, const __half* __restrict__ Wlo,
               __half* __restrict__ Couth,
               const float* __restrict__ aw_src, const float* __restrict__ aw_dst) {
    extern __shared__ char dsm[];
    float* awsS = (float*)dsm;
    float* awdS = (float*)(dsm + 512);
    __half* Bh = (__half*)(dsm + 1024);
    __half* Bl = (__half*)(dsm + 35840);
    __half* Ah = (__half*)(dsm + 70656);
    const int tid = threadIdx.x;
    const int wid = tid >> 5;
    const int lane = tid & 31;
    const int row0 = blockIdx.x * 128;
    const int warp_m = wid & 3;
    const int warp_n = wid >> 2;

    if (tid < 128) {
        awsS[tid] = aw_src[tid];
        awdS[tid] = aw_dst[tid];
    }
    {
        int br = tid >> 1, cb = (tid & 1) * 64;
        const uint4* sh = (const uint4*)&Whi[br * DD + cb];
        const uint4* sl = (const uint4*)&Wlo[br * DD + cb];
        uint4* dh = (uint4*)&Bh[br * BSTRIDE + cb];
        uint4* dl = (uint4*)&Bl[br * BSTRIDE + cb];
#pragma unroll
        for (int i = 0; i < 8; i++) { dh[i] = sh[i]; dl[i] = sl[i]; }
    }
    const int ar = tid >> 1;
    const int akb = (tid & 1) * 16;
    const size_t agrow = (size_t)min(row0 + ar, NN - 1) * DD;
#define LOAD_A(c)                                                             \
    do {                                                                      \
        const uint4* sh_ = (const uint4*)&Ahi[agrow + (c) * 32 + akb];        \
        uint4* dh_ = (uint4*)&Ah[ar * ASTRIDE + akb];                         \
        dh_[0] = sh_[0]; dh_[1] = sh_[1];                                     \
    } while (0)

    wmma::fragment<wmma::accumulator, 16, 16, 16, float> acc[2][4];
#pragma unroll
    for (int im = 0; im < 2; im++)
#pragma unroll
        for (int in = 0; in < 4; in++) wmma::fill_fragment(acc[im][in], 0.f);

    LOAD_A(0);
    __syncthreads();

#pragma unroll
    for (int c = 0; c < 4; c++) {
#pragma unroll
        for (int ksl = 0; ksl < 2; ksl++) {
            wmma::fragment<wmma::matrix_a, 16, 16, 16, __half, wmma::row_major> ah[2];
#pragma unroll
            for (int im = 0; im < 2; im++)
                wmma::load_matrix_sync(ah[im], &Ah[(warp_m * 32 + im * 16) * ASTRIDE + ksl * 16], ASTRIDE);
            const int krow = c * 32 + ksl * 16;
#pragma unroll
            for (int in = 0; in < 4; in++) {
                wmma::fragment<wmma::matrix_b, 16, 16, 16, __half, wmma::row_major> bh, bl;
                wmma::load_matrix_sync(bh, &Bh[krow * BSTRIDE + warp_n * 64 + in * 16], BSTRIDE);
                wmma::load_matrix_sync(bl, &Bl[krow * BSTRIDE + warp_n * 64 + in * 16], BSTRIDE);
#pragma unroll
                for (int im = 0; im < 2; im++) {
                    wmma::mma_sync(acc[im][in], ah[im], bh, acc[im][in]);
                    wmma::mma_sync(acc[im][in], ah[im], bl, acc[im][in]);
                }
            }
        }
        __syncthreads();
        if (c < 3) {
            LOAD_A(c + 1);
            __syncthreads();
        }
    }

    float* osm = (float*)(dsm + 1024);
#pragma unroll
    for (int im = 0; im < 2; im++)
#pragma unroll
        for (int in = 0; in < 4; in++)
            wmma::store_matrix_sync(&osm[(warp_m * 32 + im * 16) * BSTRIDE + warp_n * 64 + in * 16],
                                    acc[im][in], BSTRIDE, wmma::mem_row_major);
    __syncthreads();

    if (wid < 4) {
        int r = wid * 32 + lane;
        int grow = row0 + r;
        if (grow < NN) {
#pragma unroll
            for (int b = 0; b < 4; b++) {
                float asum = 0.f, dsum = 0.f;
#pragma unroll
                for (int i = 0; i < 32; i++) {
                    float v = osm[r * BSTRIDE + b * 32 + i];
                    asum = fmaf(v, awsS[b * 32 + i], asum);
                    dsum = fmaf(v, awdS[b * 32 + i], dsum);
                }
                g_asrc[grow * 4 + b] = asum;
                g_adst[grow * 4 + b] = dsum;
            }
        }
    }
    for (int idx = tid; idx < 128 * 32; idx += 256) {
        int r = idx >> 5;
        int c4 = (idx & 31) << 2;
        if (row0 + r < NN) {
            float4 v = *(const float4*)&osm[r * BSTRIDE + c4];
            __half2 h0 = __floats2half2_rn(v.x, v.y);
            __half2 h1 = __floats2half2_rn(v.z, v.w);
            uint2 o;
            o.x = *(uint32_t*)&h0;
            o.y = *(uint32_t*)&h1;
            *(uint2*)&Couth[(size_t)(row0 + r) * DD + c4] = o;
        }
    }
#undef LOAD_A
}

// ---------------- fused GAT aggregate layer (fp16 state) -----------------
__global__ __launch_bounds__(256) void k_gat(const __half* __restrict__ hlin,
                                             const __half* __restrict__ hprev,
                                             const float* __restrict__ bias,
                                             const float* __restrict__ gam,
                                             const float* __restrict__ bet,
                                             float* __restrict__ outp,
                                             __half* __restrict__ oh,
                                             int residual, int wh, int wf32) {
    int n = (blockIdx.x * blockDim.x + threadIdx.x) >> 5;
    if (n >= NN) return;
    const int lane = threadIdx.x & 31;
    const int hd = lane >> 3;
    const int rs = g_rowptr[n], re = g_rowptr[n + 1];

    float4 ad4 = *(const float4*)&g_adst[n * 4];
    float4 as4 = *(const float4*)&g_asrc[n * 4];

    float wslf;
    {
        float lx = (hd == 0) ? (as4.x + ad4.x) : (hd == 1) ? (as4.y + ad4.y)
                 : (hd == 2) ? (as4.z + ad4.z) : (as4.w + ad4.w);
        wslf = __expf(lrelu(lx));
    }
    float z = wslf;

    const char* hb = (const char*)hlin + lane * 8;   // lane-offset base
    uint2 sp = *(const uint2*)(hb + (size_t)n * 256);
    float2 sf01 = __half22float2(*(__half2*)&sp.x);
    float2 sf23 = __half22float2(*(__half2*)&sp.y);
    float a0 = sf01.x * wslf, a1 = sf01.y * wslf, a2 = sf23.x * wslf, a3 = sf23.y * wslf;

    const __half* ewp = g_ewh + hd;                  // per-head weight base

#pragma unroll 8
    for (int e = rs; e < re; e++) {
        int off = __ldg(&g_colb[e]);                 // uniform broadcast (L1)
        float wj = __half2float(__ldg(&ewp[(size_t)e * 4]));
        uint2 p = *(const uint2*)(hb + off);
        float2 f01 = __half22float2(*(__half2*)&p.x);
        float2 f23 = __half22float2(*(__half2*)&p.y);
        a0 = fmaf(f01.x, wj, a0);
        a1 = fmaf(f01.y, wj, a1);
        a2 = fmaf(f23.x, wj, a2);
        a3 = fmaf(f23.y, wj, a3);
        z += wj;
    }
    float invz = 1.f / (z + 1e-16f);
    a0 *= invz; a1 *= invz; a2 *= invz; a3 *= invz;

    float4 bv = *(const float4*)&bias[lane * 4];
    a0 += bv.x; a1 += bv.y; a2 += bv.z; a3 += bv.w;
    float sm = a0 + a1 + a2 + a3;
#pragma unroll
    for (int o = 16; o >= 1; o >>= 1) sm += __shfl_xor_sync(0xffffffffu, sm, o);
    float mean = sm * (1.f / DD);
    float d0 = a0 - mean, d1 = a1 - mean, d2 = a2 - mean, d3 = a3 - mean;
    float sq = d0 * d0 + d1 * d1 + d2 * d2 + d3 * d3;
#pragma unroll
    for (int o = 16; o >= 1; o >>= 1) sq += __shfl_xor_sync(0xffffffffu, sq, o);
    float rstd = rsqrtf(sq * (1.f / DD) + 1e-5f);
    float4 gv = *(const float4*)&gam[lane * 4];
    float4 bev = *(const float4*)&bet[lane * 4];
    float v0 = d0 * rstd * gv.x + bev.x;
    float v1 = d1 * rstd * gv.y + bev.y;
    float v2 = d2 * rstd * gv.z + bev.z;
    float v3 = d3 * rstd * gv.w + bev.w;
    v0 = v0 > 0.f ? v0 : __expf(v0) - 1.f;
    v1 = v1 > 0.f ? v1 : __expf(v1) - 1.f;
    v2 = v2 > 0.f ? v2 : __expf(v2) - 1.f;
    v3 = v3 > 0.f ? v3 : __expf(v3) - 1.f;
    if (residual) {
        uint2 ph = *(const uint2*)&hprev[(size_t)n * DD + lane * 4];
        float2 h01 = __half22float2(*(__half2*)&ph.x);
        float2 h23 = __half22float2(*(__half2*)&ph.y);
        v0 += h01.x;
        v1 += h01.y;
        v2 += h23.x;
        v3 += h23.y;
    }
    if (wf32) {
        *(float4*)&outp[(size_t)n * DD + lane * 4] = make_float4(v0, v1, v2, v3);
    }
    if (wh) {
        __half2 h0 = __floats2half2_rn(v0, v1);
        __half2 h1 = __floats2half2_rn(v2, v3);
        uint2 ph;
        ph.x = *(uint32_t*)&h0;
        ph.y = *(uint32_t*)&h1;
        *(uint2*)&oh[(size_t)n * DD + lane * 4] = ph;
    }
}

// ---------------- graph pooling ----------------
__global__ __launch_bounds__(128) void k_pool(const float* __restrict__ ne,
                                              const int* __restrict__ batch,
                                              float* __restrict__ gout) {
    int base = blockIdx.x * 128;
    if (base >= NN) return;
    int d = threadIdx.x;
    int end = base + 128;
    if (end > NN) end = NN;
    float acc = 0.f;
    int cg = __ldg(&batch[base]);
    for (int n = base; n < end; n++) {
        int gidx = __ldg(&batch[n]);
        if (gidx != cg) {
            atomicAdd(&gout[cg * DD + d], acc);
            acc = 0.f;
            cg = gidx;
        }
        acc += ne[(size_t)n * DD + d];
    }
    atomicAdd(&gout[cg * DD + d], acc);
}

// per-graph counts via binary search on sorted batch
__global__ void k_final(float* __restrict__ gout, const int* __restrict__ batch) {
    int g = blockIdx.x;
    int d = threadIdx.x;
    __shared__ int cnt_s;
    if (d == 0) {
        int lo = 0, hi = NN;
        while (lo < hi) { int m = (lo + hi) >> 1; if (batch[m] < g) lo = m + 1; else hi = m; }
        int lb = lo;
        lo = lb; hi = NN;
        while (lo < hi) { int m = (lo + hi) >> 1; if (batch[m] < g + 1) lo = m + 1; else hi = m; }
        cnt_s = lo - lb;
    }
    __syncthreads();
    gout[g * DD + d] /= fmaxf((float)cnt_s, 1.f);
}

// ---------------- host launch ----------------
extern "C" void kernel_launch(void* const* d_in, const int* in_sizes, int n_in,
                              void* d_out, int out_size) {
    const float* x    = (const float*)d_in[0];
    const int*   ei   = (const int*)d_in[1];
    const int*   batch= (const int*)d_in[2];
    const float* W0   = (const float*)d_in[3];
    const float* as0  = (const float*)d_in[4];
    const float* ad0  = (const float*)d_in[5];
    const float* b0   = (const float*)d_in[6];
    const float* Ws   = (const float*)d_in[7];
    const float* asr  = (const float*)d_in[8];
    const float* ads  = (const float*)d_in[9];
    const float* bs   = (const float*)d_in[10];
    const float* lng  = (const float*)d_in[11];
    const float* lnb  = (const float*)d_in[12];
    float* out  = (float*)d_out;
    float* gout = out + (size_t)NN * DD;

    __half *hX, *hY, *hlinh, *Whi, *Wlo;
    cudaGetSymbolAddress((void**)&hX, g_hX);
    cudaGetSymbolAddress((void**)&hY, g_hY);
    cudaGetSymbolAddress((void**)&hlinh, g_hlinh);
    cudaGetSymbolAddress((void**)&Whi, g_Whi);
    cudaGetSymbolAddress((void**)&Wlo, g_Wlo);

    cudaFuncSetAttribute(k_gemm_tc, cudaFuncAttributeMaxDynamicSharedMemorySize, SMEM_TC2);

    // CSR build + init (parallel 3-kernel scan)
    k_zero<<<(NN + 255) / 256, 256>>>(gout, Ws);
    k_count<<<(EE + 255) / 256, 256>>>(ei);
    k_scan_block<<<NB1, 1024>>>();
    k_scan_bsums<<<1, 128>>>();
    k_scan_add<<<(NN + 255) / 256, 256>>>();
    k_fill<<<(EE + 255) / 256, 256>>>(ei);

    // layer 0: h_0 -> X
    k_gemm0<<<(NN + 7) / 8, 128>>>(x, W0, as0, ad0, hlinh);
    k_ew<<<(EE + 255) / 256, 256>>>();
    k_gat<<<(NN * 32 + 255) / 256, 256>>>(hlinh, nullptr, b0, lng, lnb,
                                          nullptr, hX, 0, 1, 0);

    // layer 1: reads X, writes Y
    k_gemm_tc<<<(NN + 127) / 128, 256, SMEM_TC2>>>(hX, Whi, Wlo, hlinh, asr, ads);
    k_ew<<<(EE + 255) / 256, 256>>>();
    k_gat<<<(NN * 32 + 255) / 256, 256>>>(hlinh, hX, bs, lng + DD, lnb + DD,
                                          nullptr, hY, 1, 1, 0);

    // layer 2: reads Y, writes X
    k_gemm_tc<<<(NN + 127) / 128, 256, SMEM_TC2>>>(hY, Whi + DD * DD, Wlo + DD * DD,
                                                   hlinh, asr + DD, ads + DD);
    k_ew<<<(EE + 255) / 256, 256>>>();
    k_gat<<<(NN * 32 + 255) / 256, 256>>>(hlinh, hY, bs + DD, lng + 2 * DD, lnb + 2 * DD,
                                          nullptr, hX, 1, 1, 0);

    // layer 3: reads X, writes fp32 out
    k_gemm_tc<<<(NN + 127) / 128, 256, SMEM_TC2>>>(hX, Whi + 2 * DD * DD, Wlo + 2 * DD * DD,
                                                   hlinh, asr + 2 * DD, ads + 2 * DD);
    k_ew<<<(EE + 255) / 256, 256>>>();
    k_gat<<<(NN * 32 + 255) / 256, 256>>>(hlinh, hX, bs + 2 * DD, lng + 3 * DD, lnb + 3 * DD,
                                          out, nullptr, 1, 0, 1);

    // graph mean pooling
    k_pool<<<(NN + 127) / 128, 128>>>(out, batch, gout);
    k_final<<<GG, 128>>>(gout, batch);
}